// round 8
// baseline (speedup 1.0000x reference)
#include <cuda_runtime.h>
#include <cuda_bf16.h>
#include <math.h>
#include <stdint.h>

#define NPIX 16384
#define CDIM 128
#define NB 2
#define NV 6
#define BVI 12
#define WW 128

typedef uint16_t u16;
typedef uint32_t u32;

// ---------------- scratch ----------------
__device__ float g_bufA[(size_t)BVI * CDIM * NPIX];
__device__ float g_bufB[(size_t)BVI * CDIM * NPIX];
__device__ float g_bufC[(size_t)BVI * CDIM * NPIX];
__device__ float g_alp [(size_t)BVI * NPIX];
__device__ float g_pool[(size_t)NB * CDIM * NPIX];
__device__ float g_u   [(size_t)NB * CDIM * NPIX];
// weight hi/lo planes (k-major rows; GRU weights row-interleaved hidden/gate)
__device__ __align__(16) u16 g_wm1h[128 * 256], g_wm1l[128 * 256];
__device__ __align__(16) u16 g_wm2h[128 * 128], g_wm2l[128 * 128];
__device__ __align__(16) u16 g_wgh [256 * 128], g_wgl [256 * 128];
__device__ __align__(16) u16 g_wgbh[256 * 128], g_wgbl[256 * 128];
__device__ __align__(16) u16 g_wuph[128 * 128], g_wupl[128 * 128];

__device__ __forceinline__ float gelu_exact(float x) {
    return 0.5f * x * (1.0f + erff(x * 0.70710678118654752f));
}
__device__ __forceinline__ u32 smem_u32(const void* p) {
    return (u32)__cvta_generic_to_shared(p);
}
__device__ __forceinline__ void split_pack(float v0, float v1, u32& hi, u32& lo) {
    asm("cvt.rn.bf16x2.f32 %0, %1, %2;" : "=r"(hi) : "f"(v1), "f"(v0));
    float r0 = v0 - __uint_as_float(hi << 16);
    float r1 = v1 - __uint_as_float(hi & 0xffff0000u);
    asm("cvt.rn.bf16x2.f32 %0, %1, %2;" : "=r"(lo) : "f"(r1), "f"(r0));
}
__device__ __forceinline__ void ldm_x4(u32* r, u32 addr) {
    asm volatile("ldmatrix.sync.aligned.m8n8.x4.shared.b16 {%0,%1,%2,%3}, [%4];"
                 : "=r"(r[0]), "=r"(r[1]), "=r"(r[2]), "=r"(r[3]) : "r"(addr));
}
__device__ __forceinline__ void ldm_x4t(u32* r, u32 addr) {
    asm volatile("ldmatrix.sync.aligned.m8n8.x4.trans.shared.b16 {%0,%1,%2,%3}, [%4];"
                 : "=r"(r[0]), "=r"(r[1]), "=r"(r[2]), "=r"(r[3]) : "r"(addr));
}
__device__ __forceinline__ void mma_bf16(float* d, const u32* a, const u32* b) {
    asm volatile(
        "mma.sync.aligned.m16n8k16.row.col.f32.bf16.bf16.f32 "
        "{%0,%1,%2,%3}, {%4,%5,%6,%7}, {%8,%9}, {%0,%1,%2,%3};"
        : "+f"(d[0]), "+f"(d[1]), "+f"(d[2]), "+f"(d[3])
        : "r"(a[0]), "r"(a[1]), "r"(a[2]), "r"(a[3]), "r"(b[0]), "r"(b[1]));
}
__device__ __forceinline__ void cpasync16(u32 dst, const void* src) {
    asm volatile("cp.async.cg.shared.global [%0], [%1], 16;" :: "r"(dst), "l"(src));
}
__device__ __forceinline__ void cp_commit() {
    asm volatile("cp.async.commit_group;" ::: "memory");
}

// ================= generic GEMM (merge1 / merge2 / up) =================
constexpr int KC = 32;
constexpr int A_PITCH_B = 80;
constexpr int A_PLANE_B = 128 * A_PITCH_B;
constexpr int A_STAGE_B = 2 * A_PLANE_B;
constexpr int BF32_PITCH = 528;
constexpr int BF32_STAGE = KC * BF32_PITCH;
constexpr int BB_PITCH = 272;
constexpr int BB_PLANE = KC * BB_PITCH;
constexpr int OFF_A0  = 0;
constexpr int OFF_A1  = A_STAGE_B;
constexpr int OFF_F0  = 2 * A_STAGE_B;
constexpr int OFF_F1  = OFF_F0 + BF32_STAGE;
constexpr int OFF_BH  = OFF_F1 + BF32_STAGE;
constexpr int OFF_BL  = OFF_BH + BB_PLANE;
constexpr int GSMEM   = OFF_BL + BB_PLANE;

template <int KTOT, int MTOT, int EPI, bool SPLIT>
__global__ __launch_bounds__(256, 2) void gemm_mma(
    const float* __restrict__ X0, const float* __restrict__ X1,
    const u16* __restrict__ Wh_g, const u16* __restrict__ Wl_g,
    const float* __restrict__ Bias, const float* __restrict__ Res,
    float* __restrict__ Out)
{
    extern __shared__ __align__(16) char sm[];
    const u32 sm0 = smem_u32(sm);

    const int img = blockIdx.z;
    const int p0  = blockIdx.x * 128;
    const int m0  = blockIdx.y * 128;
    const int tid = threadIdx.x;
    const int lane = tid & 31, wid = tid >> 5;
    const int wm = wid >> 2, wn = wid & 3;

    float acc[4][4][4];
#pragma unroll
    for (int i = 0; i < 4; i++)
#pragma unroll
        for (int j = 0; j < 4; j++)
#pragma unroll
            for (int q = 0; q < 4; q++) acc[i][j][q] = 0.f;

    constexpr int NCH = KTOT / KC;

    auto copyAB = [&](int c, int s) {
        const int kbase = c * KC;
        const float* Xc = X0;
        int kb = kbase;
        if (SPLIT && kbase >= 128) { Xc = X1; kb = kbase - 128; }
        const size_t bbase = ((size_t)img * (SPLIT ? 128 : KTOT) + kb) * NPIX + p0;
        const u32 fdst = sm0 + (s ? OFF_F1 : OFF_F0);
#pragma unroll
        for (int i = 0; i < 4; i++) {
            int idx = tid + i * 256;
            int row = idx >> 5, seg = idx & 31;
            cpasync16(fdst + row * BF32_PITCH + seg * 16,
                      Xc + bbase + (size_t)row * NPIX + seg * 4);
        }
        const size_t abase = (size_t)m0 * KTOT + kbase;
        const u32 adst = sm0 + (s ? OFF_A1 : OFF_A0);
#pragma unroll
        for (int i = 0; i < 4; i++) {
            int idx = tid + i * 256;
            int plane = idx >> 9, rem = idx & 511;
            int row = rem >> 2, seg = rem & 3;
            const u16* src = (plane ? Wl_g : Wh_g) + abase + (size_t)row * KTOT + seg * 8;
            cpasync16(adst + plane * A_PLANE_B + row * A_PITCH_B + seg * 16, src);
        }
    };

    const int lr  = lane & 7;
    const int lth = (lane >> 3) & 1;
    const int ltv = lane >> 4;
    const u32 a_row = (u32)(wm * 64 + lth * 8 + lr);

    copyAB(0, 0); cp_commit();

#pragma unroll 1
    for (int c = 0; c < NCH; c++) {
        const int s = c & 1;
        __syncthreads();
        if (c + 1 < NCH) {
            copyAB(c + 1, s ^ 1); cp_commit();
            asm volatile("cp.async.wait_group 1;" ::: "memory");
        } else {
            asm volatile("cp.async.wait_group 0;" ::: "memory");
        }
        __syncthreads();

        {
            const char* fsrc = sm + (s ? OFF_F1 : OFF_F0);
#pragma unroll
            for (int i = 0; i < 8; i++) {
                int p = tid + i * 256;
                int row = p >> 6, cp2 = p & 63;
                float2 v = *reinterpret_cast<const float2*>(fsrc + row * BF32_PITCH + cp2 * 8);
                u32 hi, lo;
                split_pack(v.x, v.y, hi, lo);
                *reinterpret_cast<u32*>(sm + OFF_BH + row * BB_PITCH + cp2 * 4) = hi;
                *reinterpret_cast<u32*>(sm + OFF_BL + row * BB_PITCH + cp2 * 4) = lo;
            }
        }
        __syncthreads();

        const u32 ah = sm0 + (s ? OFF_A1 : OFF_A0);
        const u32 al = ah + A_PLANE_B;
        const u32 bh = sm0 + OFF_BH, bl = sm0 + OFF_BL;

#pragma unroll
        for (int kk = 0; kk < KC / 16; kk++) {
            u32 af[4][4];
            u32 bfh[4][2], bfl[4][2];
            const u32 a_off = a_row * A_PITCH_B + kk * 32 + ltv * 16;
            const u32 b_off = (u32)(kk * 16 + lth * 8 + lr) * BB_PITCH + wn * 64 + ltv * 16;
#pragma unroll
            for (int mf = 0; mf < 4; mf++)
                ldm_x4(af[mf], ah + a_off + mf * 16 * A_PITCH_B);
#pragma unroll
            for (int nh = 0; nh < 2; nh++) {
                u32 r[4];
                ldm_x4t(r, bh + b_off + nh * 32);
                bfh[nh * 2][0] = r[0]; bfh[nh * 2][1] = r[1];
                bfh[nh * 2 + 1][0] = r[2]; bfh[nh * 2 + 1][1] = r[3];
            }
#pragma unroll
            for (int mf = 0; mf < 4; mf++)
#pragma unroll
                for (int nf = 0; nf < 4; nf++)
                    mma_bf16(acc[mf][nf], af[mf], bfh[nf]);
#pragma unroll
            for (int nh = 0; nh < 2; nh++) {
                u32 r[4];
                ldm_x4t(r, bl + b_off + nh * 32);
                bfl[nh * 2][0] = r[0]; bfl[nh * 2][1] = r[1];
                bfl[nh * 2 + 1][0] = r[2]; bfl[nh * 2 + 1][1] = r[3];
            }
#pragma unroll
            for (int mf = 0; mf < 4; mf++)
#pragma unroll
                for (int nf = 0; nf < 4; nf++)
                    mma_bf16(acc[mf][nf], af[mf], bfl[nf]);
#pragma unroll
            for (int mf = 0; mf < 4; mf++)
                ldm_x4(af[mf], al + a_off + mf * 16 * A_PITCH_B);
#pragma unroll
            for (int mf = 0; mf < 4; mf++)
#pragma unroll
                for (int nf = 0; nf < 4; nf++)
                    mma_bf16(acc[mf][nf], af[mf], bfh[nf]);
        }
    }

    const int g = lane >> 2, tg = lane & 3;
#pragma unroll
    for (int mf = 0; mf < 4; mf++) {
#pragma unroll
        for (int half = 0; half < 2; half++) {
            const int m = m0 + wm * 64 + mf * 16 + half * 8 + g;
            const float bias = Bias ? Bias[m] : 0.f;
            const size_t rowb = ((size_t)img * MTOT + m) * NPIX;
            const float* resrow = (EPI == 2) ? &Res[((size_t)img * CDIM + m) * NPIX] : nullptr;
#pragma unroll
            for (int nf = 0; nf < 4; nf++) {
                const int px = p0 + wn * 32 + nf * 8 + 2 * tg;
                float v0 = acc[mf][nf][half * 2 + 0] + bias;
                float v1 = acc[mf][nf][half * 2 + 1] + bias;
                if (EPI == 1) { v0 = gelu_exact(v0); v1 = gelu_exact(v1); }
                if (EPI == 2) { v0 += resrow[px]; v1 += resrow[px + 1]; }
                *reinterpret_cast<float2*>(&Out[rowb + px]) = make_float2(v0, v1);
            }
        }
    }
}

// ================= fused GRU: (C->2C linear over V) + minGRU scan =================
// A rows interleaved: row 2c = W_hidden[c], row 2c+1 = W_gate[c].
// CTA tile: 256 out-rows x 64 pixels; iterates v=0..5, h-state in smem.
constexpr int GA_PITCH = 80;
constexpr int GA_PLANE = 256 * GA_PITCH;         // 20480
constexpr int GF_PITCH = 272;
constexpr int GF_STAGE = 32 * GF_PITCH;          // 8704
constexpr int GB_PITCH = 144;
constexpr int GB_PLANE = 32 * GB_PITCH;          // 4608
constexpr int G_OFF_F0 = 2 * GA_PLANE;           // 40960
constexpr int G_OFF_F1 = G_OFF_F0 + GF_STAGE;
constexpr int G_OFF_BH = G_OFF_F1 + GF_STAGE;
constexpr int G_OFF_BL = G_OFF_BH + GB_PLANE;
constexpr int G_OFF_H  = G_OFF_BL + GB_PLANE;    // 67584
constexpr int GSMEM_G  = G_OFF_H + 128 * 64 * 4; // 100352

__global__ __launch_bounds__(256, 2) void gru_fused(
    const float* __restrict__ X, const u16* __restrict__ Wh_g,
    const u16* __restrict__ Wl_g, float* __restrict__ Out)
{
    extern __shared__ __align__(16) char sm[];
    const u32 sm0 = smem_u32(sm);
    const int b  = blockIdx.z;
    const int p0 = blockIdx.x * 64;
    const int tid = threadIdx.x;
    const int lane = tid & 31, wid = tid >> 5;
    const int wm = wid >> 1, wn = wid & 1;         // 4 m-warps x 2 n-warps
    const int lr = lane & 7, lth = (lane >> 3) & 1, ltv = lane >> 4;
    const int g = lane >> 2, tg = lane & 3;
    const u32 a_row = (u32)(wm * 64 + lth * 8 + lr);

    // zero h state
#pragma unroll
    for (int i = tid; i < 128 * 64 / 4; i += 256)
        reinterpret_cast<float4*>(sm + G_OFF_H)[i] = make_float4(0.f, 0.f, 0.f, 0.f);

    float acc[4][4][4];
#pragma unroll
    for (int i = 0; i < 4; i++)
#pragma unroll
        for (int j = 0; j < 4; j++)
#pragma unroll
            for (int q = 0; q < 4; q++) acc[i][j][q] = 0.f;

    auto copyA = [&](int c) {
#pragma unroll
        for (int i = 0; i < 8; i++) {
            int idx = tid + i * 256;
            int plane = idx >> 10, rem = idx & 1023;
            int row = rem >> 2, seg = rem & 3;
            const u16* src = (plane ? Wl_g : Wh_g) + (size_t)row * 128 + c * 32 + seg * 8;
            cpasync16(sm0 + plane * GA_PLANE + row * GA_PITCH + seg * 16, src);
        }
    };
    auto copyB = [&](int it, int s) {
        int v = it >> 2, c = it & 3;
        const size_t bbase = ((size_t)(b * NV + v) * 128 + c * 32) * NPIX + p0;
#pragma unroll
        for (int i = 0; i < 2; i++) {
            int idx = tid + i * 256;
            int row = idx >> 4, seg = idx & 15;
            cpasync16(sm0 + (s ? G_OFF_F1 : G_OFF_F0) + row * GF_PITCH + seg * 16,
                      X + bbase + (size_t)row * NPIX + seg * 4);
        }
    };

    copyB(0, 0); cp_commit();

#pragma unroll 1
    for (int it = 0; it < 4 * NV; it++) {
        const int s = it & 1;
        __syncthreads();                 // prior A/B-bf16 reads done
        copyA(it & 3); cp_commit();
        if (it + 1 < 4 * NV) {
            copyB(it + 1, s ^ 1); cp_commit();
            asm volatile("cp.async.wait_group 1;" ::: "memory");
        } else {
            asm volatile("cp.async.wait_group 0;" ::: "memory");
        }
        __syncthreads();

        // convert B fp32 stage -> bf16 planes
        {
            const char* fsrc = sm + (s ? G_OFF_F1 : G_OFF_F0);
#pragma unroll
            for (int i = 0; i < 4; i++) {
                int p = tid + i * 256;
                int row = p >> 5, cp2 = p & 31;
                float2 v = *reinterpret_cast<const float2*>(fsrc + row * GF_PITCH + cp2 * 8);
                u32 hi, lo;
                split_pack(v.x, v.y, hi, lo);
                *reinterpret_cast<u32*>(sm + G_OFF_BH + row * GB_PITCH + cp2 * 4) = hi;
                *reinterpret_cast<u32*>(sm + G_OFF_BL + row * GB_PITCH + cp2 * 4) = lo;
            }
        }
        __syncthreads();

        const u32 ah = sm0, al = sm0 + GA_PLANE;
        const u32 bh = sm0 + G_OFF_BH, bl = sm0 + G_OFF_BL;
#pragma unroll
        for (int kk = 0; kk < 2; kk++) {
            u32 af[4][4];
            u32 bfh[4][2], bfl[4][2];
            const u32 a_off = a_row * GA_PITCH + kk * 32 + ltv * 16;
            const u32 b_off = (u32)(kk * 16 + lth * 8 + lr) * GB_PITCH + wn * 64 + ltv * 16;
#pragma unroll
            for (int mf = 0; mf < 4; mf++)
                ldm_x4(af[mf], ah + a_off + mf * 16 * GA_PITCH);
#pragma unroll
            for (int nh = 0; nh < 2; nh++) {
                u32 r[4];
                ldm_x4t(r, bh + b_off + nh * 32);
                bfh[nh * 2][0] = r[0]; bfh[nh * 2][1] = r[1];
                bfh[nh * 2 + 1][0] = r[2]; bfh[nh * 2 + 1][1] = r[3];
            }
#pragma unroll
            for (int mf = 0; mf < 4; mf++)
#pragma unroll
                for (int nf = 0; nf < 4; nf++)
                    mma_bf16(acc[mf][nf], af[mf], bfh[nf]);
#pragma unroll
            for (int nh = 0; nh < 2; nh++) {
                u32 r[4];
                ldm_x4t(r, bl + b_off + nh * 32);
                bfl[nh * 2][0] = r[0]; bfl[nh * 2][1] = r[1];
                bfl[nh * 2 + 1][0] = r[2]; bfl[nh * 2 + 1][1] = r[3];
            }
#pragma unroll
            for (int mf = 0; mf < 4; mf++)
#pragma unroll
                for (int nf = 0; nf < 4; nf++)
                    mma_bf16(acc[mf][nf], af[mf], bfl[nf]);
#pragma unroll
            for (int mf = 0; mf < 4; mf++)
                ldm_x4(af[mf], al + a_off + mf * 16 * GA_PITCH);
#pragma unroll
            for (int mf = 0; mf < 4; mf++)
#pragma unroll
                for (int nf = 0; nf < 4; nf++)
                    mma_bf16(acc[mf][nf], af[mf], bfh[nf]);
        }

        // end of view: scan epilogue (shfl hidden/gate exchange; h in smem, per-thread-owned)
        if ((it & 3) == 3) {
            const int v = it >> 2;
#pragma unroll
            for (int mf = 0; mf < 4; mf++) {
#pragma unroll
                for (int nf = 0; nf < 4; nf++) {
#pragma unroll
                    for (int half = 0; half < 2; half++) {
                        float a0 = acc[mf][nf][half * 2 + 0];
                        float a1 = acc[mf][nf][half * 2 + 1];
                        float b0 = __shfl_xor_sync(0xffffffffu, a0, 4);
                        float b1 = __shfl_xor_sync(0xffffffffu, a1, 4);
                        if (!(g & 1)) {   // hidden-parity lanes own channel c
                            int row = wm * 64 + mf * 16 + half * 8 + g;
                            int c = row >> 1;
                            int pxl = wn * 32 + nf * 8 + 2 * tg;
                            float2* hp = reinterpret_cast<float2*>(
                                sm + G_OFF_H + (c * 64 + pxl) * 4);
                            float2 h = *hp;
                            float z0 = 1.f / (1.f + expf(-b0));
                            float ht0 = (a0 >= 0.f) ? (a0 + 0.5f) : (1.f / (1.f + expf(-a0)));
                            h.x = (1.f - z0) * h.x + z0 * ht0;
                            float z1 = 1.f / (1.f + expf(-b1));
                            float ht1 = (a1 >= 0.f) ? (a1 + 0.5f) : (1.f / (1.f + expf(-a1)));
                            h.y = (1.f - z1) * h.y + z1 * ht1;
                            *hp = h;
                            *reinterpret_cast<float2*>(
                                &Out[((size_t)(b * NV + v) * 128 + c) * NPIX + p0 + pxl]) = h;
                        }
                        acc[mf][nf][half * 2 + 0] = 0.f;
                        acc[mf][nf][half * 2 + 1] = 0.f;
                    }
                }
            }
        }
    }
}

// ---------------- weight prep (GRU rows interleaved) ----------------
__global__ void prep_w_all(
    const float* __restrict__ w1, const float* __restrict__ w2,
    const float* __restrict__ wg, const float* __restrict__ wgb,
    const float* __restrict__ wup,
    u16* __restrict__ w1h, u16* __restrict__ w1l,
    u16* __restrict__ w2h, u16* __restrict__ w2l,
    u16* __restrict__ wgh, u16* __restrict__ wgl,
    u16* __restrict__ wgbh, u16* __restrict__ wgbl,
    u16* __restrict__ wuph, u16* __restrict__ wupl)
{
    int i = blockIdx.x * 256 + threadIdx.x;
    float v; u16 *dh, *dl; int off;
    if      (i < 32768)  { off = i;          v = w1[off];  dh = w1h;  dl = w1l; }
    else if (i < 49152)  { off = i - 32768;  v = w2[off];  dh = w2h;  dl = w2l; }
    else if (i < 81920)  { off = i - 49152;
        int r = off >> 7, k = off & 127;
        int sr = (r & 1) ? 128 + (r >> 1) : (r >> 1);
        v = wg[sr * 128 + k]; dh = wgh; dl = wgl; }
    else if (i < 114688) { off = i - 81920;
        int r = off >> 7, k = off & 127;
        int sr = (r & 1) ? 128 + (r >> 1) : (r >> 1);
        v = wgb[sr * 128 + k]; dh = wgbh; dl = wgbl; }
    else                 { off = i - 114688; v = wup[off]; dh = wuph; dl = wupl; }
    float hf = __bfloat162float(__float2bfloat16(v));
    dh[off] = (u16)(__float_as_uint(hf) >> 16);
    dl[off] = (u16)(__float_as_uint(__bfloat162float(__float2bfloat16(v - hf))) >> 16);
}

// ---------------- depthwise 3x3 + bias + GELU ----------------
__global__ __launch_bounds__(256) void dw3x3(
    const float* __restrict__ in, const float* __restrict__ wd,
    const float* __restrict__ bd, float* __restrict__ out)
{
    int c = blockIdx.y, img = blockIdx.z;
    int pix = blockIdx.x * 256 + threadIdx.x;
    int h = pix >> 7, w = pix & 127;
    const float* p = in + ((size_t)img * CDIM + c) * NPIX;
    float s = bd[c];
#pragma unroll
    for (int ky = 0; ky < 3; ky++) {
        int hh = h + ky - 1;
        if ((unsigned)hh >= 128u) continue;
#pragma unroll
        for (int kx = 0; kx < 3; kx++) {
            int ww = w + kx - 1;
            if ((unsigned)ww >= 128u) continue;
            s = fmaf(wd[c * 9 + ky * 3 + kx], p[hh * WW + ww], s);
        }
    }
    out[((size_t)img * CDIM + c) * NPIX + pix] = gelu_exact(s);
}

// ---------------- alpha: 3x3 conv C->1 ----------------
__global__ __launch_bounds__(256) void alpha_conv(
    const float* __restrict__ g2, const float* __restrict__ aw,
    const float* __restrict__ ab, float* __restrict__ alpha)
{
    __shared__ float w[1152];
    for (int i = threadIdx.x; i < 1152; i += 256) w[i] = aw[i];
    __syncthreads();
    int img = blockIdx.z;
    int pix = blockIdx.x * 256 + threadIdx.x;
    int h = pix >> 7, x = pix & 127;
    float s = ab[0];
    const float* base = g2 + (size_t)img * CDIM * NPIX;
    for (int c = 0; c < CDIM; c++) {
        const float* p  = base + (size_t)c * NPIX;
        const float* wc = w + c * 9;
#pragma unroll
        for (int ky = 0; ky < 3; ky++) {
            int hh = h + ky - 1;
            if ((unsigned)hh >= 128u) continue;
#pragma unroll
            for (int kx = 0; kx < 3; kx++) {
                int ww = x + kx - 1;
                if ((unsigned)ww >= 128u) continue;
                s = fmaf(wc[ky * 3 + kx], p[hh * WW + ww], s);
            }
        }
    }
    alpha[(size_t)img * NPIX + pix] = s;
}

// ---------------- softmax over V + weighted pool ----------------
__global__ __launch_bounds__(256) void pool_k(
    const float* __restrict__ g2, const float* __restrict__ alpha, float* __restrict__ out)
{
    int b = blockIdx.z;
    int pix = blockIdx.x * 256 + threadIdx.x;
    float a[NV];
    float mx = -1e30f;
#pragma unroll
    for (int v = 0; v < NV; v++) {
        a[v] = alpha[(size_t)(b * NV + v) * NPIX + pix];
        mx = fmaxf(mx, a[v]);
    }
    float sum = 0.f;
#pragma unroll
    for (int v = 0; v < NV; v++) { a[v] = expf(a[v] - mx); sum += a[v]; }
    float inv = 1.f / sum;
#pragma unroll
    for (int v = 0; v < NV; v++) a[v] *= inv;
    for (int c = 0; c < CDIM; c++) {
        float s = 0.f;
#pragma unroll
        for (int v = 0; v < NV; v++)
            s = fmaf(a[v], g2[(((size_t)(b * NV + v)) * CDIM + c) * NPIX + pix], s);
        out[((size_t)b * CDIM + c) * NPIX + pix] = s;
    }
}

// ---------------- pixel-shuffle(4) + 3x3 conv 8->3 (512->512 resize = identity) ----------------
__global__ __launch_bounds__(256) void outc_k(
    const float* __restrict__ u, const float* __restrict__ wt,
    const float* __restrict__ bs, float* __restrict__ out)
{
    __shared__ float w[216];
    if (threadIdx.x < 216) w[threadIdx.x] = wt[threadIdx.x];
    __syncthreads();
    int b = blockIdx.z, co = blockIdx.y;
    int idx = blockIdx.x * 256 + threadIdx.x;
    int y = idx >> 9, x = idx & 511;
    float s = bs[co];
    const float* ub = u + (size_t)b * CDIM * NPIX;
#pragma unroll
    for (int ky = 0; ky < 3; ky++) {
        int yy = y + ky - 1;
        if ((unsigned)yy >= 512u) continue;
        int sy = yy & 3, hy = yy >> 2;
#pragma unroll
        for (int kx = 0; kx < 3; kx++) {
            int xx = x + kx - 1;
            if ((unsigned)xx >= 512u) continue;
            int sx = xx & 3, hx = xx >> 2;
            const float* up = ub + (size_t)(sy * 4 + sx) * NPIX + hy * WW + hx;
#pragma unroll
            for (int ci = 0; ci < 8; ci++)
                s = fmaf(w[(co * 8 + ci) * 9 + ky * 3 + kx], up[(size_t)ci * 16 * NPIX], s);
        }
    }
    out[((size_t)b * 3 + co) * (512 * 512) + idx] = s;
}

// ---------------- launch ----------------
extern "C" void kernel_launch(void* const* d_in, const int* in_sizes, int n_in,
                              void* d_out, int out_size)
{
    const float* feats     = (const float*)d_in[0];
    const float* prj       = (const float*)d_in[1];
    const float* merge_w1  = (const float*)d_in[2];
    const float* merge_b1  = (const float*)d_in[3];
    const float* merge_wd  = (const float*)d_in[4];
    const float* merge_bd  = (const float*)d_in[5];
    const float* merge_w2  = (const float*)d_in[6];
    const float* merge_b2  = (const float*)d_in[7];
    const float* gru_w     = (const float*)d_in[8];
    const float* gru_bw    = (const float*)d_in[9];
    const float* alpha_w   = (const float*)d_in[10];
    const float* alpha_b   = (const float*)d_in[11];
    const float* up_w      = (const float*)d_in[12];
    const float* up_b      = (const float*)d_in[13];
    const float* outc_w    = (const float*)d_in[14];
    const float* outc_b    = (const float*)d_in[15];

    float *bufA, *bufB, *bufC, *alp, *pool, *u;
    u16 *wm1h, *wm1l, *wm2h, *wm2l, *wgh, *wgl, *wgbh, *wgbl, *wuph, *wupl;
    cudaGetSymbolAddress((void**)&bufA, g_bufA);
    cudaGetSymbolAddress((void**)&bufB, g_bufB);
    cudaGetSymbolAddress((void**)&bufC, g_bufC);
    cudaGetSymbolAddress((void**)&alp,  g_alp);
    cudaGetSymbolAddress((void**)&pool, g_pool);
    cudaGetSymbolAddress((void**)&u,    g_u);
    cudaGetSymbolAddress((void**)&wm1h, g_wm1h); cudaGetSymbolAddress((void**)&wm1l, g_wm1l);
    cudaGetSymbolAddress((void**)&wm2h, g_wm2h); cudaGetSymbolAddress((void**)&wm2l, g_wm2l);
    cudaGetSymbolAddress((void**)&wgh,  g_wgh);  cudaGetSymbolAddress((void**)&wgl,  g_wgl);
    cudaGetSymbolAddress((void**)&wgbh, g_wgbh); cudaGetSymbolAddress((void**)&wgbl, g_wgbl);
    cudaGetSymbolAddress((void**)&wuph, g_wuph); cudaGetSymbolAddress((void**)&wupl, g_wupl);

    cudaFuncSetAttribute(gemm_mma<256, 128, 1, true >, cudaFuncAttributeMaxDynamicSharedMemorySize, GSMEM);
    cudaFuncSetAttribute(gemm_mma<128, 128, 2, false>, cudaFuncAttributeMaxDynamicSharedMemorySize, GSMEM);
    cudaFuncSetAttribute(gemm_mma<128, 128, 0, false>, cudaFuncAttributeMaxDynamicSharedMemorySize, GSMEM);
    cudaFuncSetAttribute(gru_fused, cudaFuncAttributeMaxDynamicSharedMemorySize, GSMEM_G);
    cudaFuncSetAttribute(gemm_mma<256, 128, 1, true >, cudaFuncAttributePreferredSharedMemoryCarveout, 100);
    cudaFuncSetAttribute(gemm_mma<128, 128, 2, false>, cudaFuncAttributePreferredSharedMemoryCarveout, 100);
    cudaFuncSetAttribute(gemm_mma<128, 128, 0, false>, cudaFuncAttributePreferredSharedMemoryCarveout, 100);
    cudaFuncSetAttribute(gru_fused, cudaFuncAttributePreferredSharedMemoryCarveout, 100);

    prep_w_all<<<512, 256>>>(merge_w1, merge_w2, gru_w, gru_bw, up_w,
                             wm1h, wm1l, wm2h, wm2l, wgh, wgl, wgbh, wgbl, wuph, wupl);

    // merge1: 1x1 (2C->C) + GELU
    gemm_mma<256, 128, 1, true ><<<dim3(128, 1, BVI), 256, GSMEM>>>(
        feats, prj, wm1h, wm1l, merge_b1, nullptr, bufA);
    // depthwise 3x3 + GELU
    dw3x3<<<dim3(64, CDIM, BVI), 256>>>(bufA, merge_wd, merge_bd, bufB);
    // merge2: 1x1 (C->C) + bias + residual
    gemm_mma<128, 128, 2, false><<<dim3(128, 1, BVI), 256, GSMEM>>>(
        bufB, nullptr, wm2h, wm2l, merge_b2, feats, bufC);
    // fused fwd GRU (linear + scan)
    gru_fused<<<dim3(NPIX / 64, 1, NB), 256, GSMEM_G>>>(bufC, wgh, wgl, bufA);
    // fused bwd GRU (H-flips cancel -> forward scan)
    gru_fused<<<dim3(NPIX / 64, 1, NB), 256, GSMEM_G>>>(bufA, wgbh, wgbl, bufB);
    // alpha conv + softmax pool
    alpha_conv<<<dim3(64, 1, BVI), 256>>>(bufB, alpha_w, alpha_b, alp);
    pool_k<<<dim3(64, 1, NB), 256>>>(bufB, alp, pool);
    // up 1x1 conv
    gemm_mma<128, 128, 0, false><<<dim3(128, 1, NB), 256, GSMEM>>>(
        pool, nullptr, wuph, wupl, up_b, nullptr, u);
    // pixel shuffle + outc 3x3
    outc_k<<<dim3(1024, 3, NB), 256>>>(u, outc_w, outc_b, (float*)d_out);
}

// round 9
// speedup vs baseline: 1.0261x; 1.0261x over previous
#include <cuda_runtime.h>
#include <cuda_bf16.h>
#include <math.h>
#include <stdint.h>

#define NPIX 16384
#define CDIM 128
#define NB 2
#define NV 6
#define BVI 12
#define WW 128

typedef uint16_t u16;
typedef uint32_t u32;

// ---------------- scratch ----------------
__device__ float g_bufA[(size_t)BVI * CDIM * NPIX];
__device__ float g_bufB[(size_t)BVI * CDIM * NPIX];
__device__ float g_bufC[(size_t)BVI * CDIM * NPIX];
__device__ float g_alp [(size_t)BVI * NPIX];
__device__ float g_pool[(size_t)NB * CDIM * NPIX];
__device__ float g_u   [(size_t)NB * CDIM * NPIX];
// weight hi/lo planes (k-major rows; GRU weights row-interleaved hidden/gate)
__device__ __align__(16) u16 g_wm1h[128 * 256], g_wm1l[128 * 256];
__device__ __align__(16) u16 g_wm2h[128 * 128], g_wm2l[128 * 128];
__device__ __align__(16) u16 g_wgh [256 * 128], g_wgl [256 * 128];
__device__ __align__(16) u16 g_wgbh[256 * 128], g_wgbl[256 * 128];
__device__ __align__(16) u16 g_wuph[128 * 128], g_wupl[128 * 128];

__device__ __forceinline__ float gelu_exact(float x) {
    return 0.5f * x * (1.0f + erff(x * 0.70710678118654752f));
}
__device__ __forceinline__ u32 smem_u32(const void* p) {
    return (u32)__cvta_generic_to_shared(p);
}
__device__ __forceinline__ void split_pack(float v0, float v1, u32& hi, u32& lo) {
    asm("cvt.rn.bf16x2.f32 %0, %1, %2;" : "=r"(hi) : "f"(v1), "f"(v0));
    float r0 = v0 - __uint_as_float(hi << 16);
    float r1 = v1 - __uint_as_float(hi & 0xffff0000u);
    asm("cvt.rn.bf16x2.f32 %0, %1, %2;" : "=r"(lo) : "f"(r1), "f"(r0));
}
__device__ __forceinline__ void ldm_x4(u32* r, u32 addr) {
    asm volatile("ldmatrix.sync.aligned.m8n8.x4.shared.b16 {%0,%1,%2,%3}, [%4];"
                 : "=r"(r[0]), "=r"(r[1]), "=r"(r[2]), "=r"(r[3]) : "r"(addr));
}
__device__ __forceinline__ void ldm_x4t(u32* r, u32 addr) {
    asm volatile("ldmatrix.sync.aligned.m8n8.x4.trans.shared.b16 {%0,%1,%2,%3}, [%4];"
                 : "=r"(r[0]), "=r"(r[1]), "=r"(r[2]), "=r"(r[3]) : "r"(addr));
}
__device__ __forceinline__ void mma_bf16(float* d, const u32* a, const u32* b) {
    asm volatile(
        "mma.sync.aligned.m16n8k16.row.col.f32.bf16.bf16.f32 "
        "{%0,%1,%2,%3}, {%4,%5,%6,%7}, {%8,%9}, {%0,%1,%2,%3};"
        : "+f"(d[0]), "+f"(d[1]), "+f"(d[2]), "+f"(d[3])
        : "r"(a[0]), "r"(a[1]), "r"(a[2]), "r"(a[3]), "r"(b[0]), "r"(b[1]));
}
__device__ __forceinline__ void cpasync16(u32 dst, const void* src) {
    asm volatile("cp.async.cg.shared.global [%0], [%1], 16;" :: "r"(dst), "l"(src));
}
__device__ __forceinline__ void cp_commit() {
    asm volatile("cp.async.commit_group;" ::: "memory");
}

// ================= generic GEMM (merge1 / merge2 / up) =================
constexpr int KC = 32;
constexpr int A_PITCH_B = 80;
constexpr int A_PLANE_B = 128 * A_PITCH_B;
constexpr int A_STAGE_B = 2 * A_PLANE_B;
constexpr int BF32_PITCH = 528;
constexpr int BF32_STAGE = KC * BF32_PITCH;
constexpr int BB_PITCH = 272;
constexpr int BB_PLANE = KC * BB_PITCH;
constexpr int OFF_A0  = 0;
constexpr int OFF_A1  = A_STAGE_B;
constexpr int OFF_F0  = 2 * A_STAGE_B;
constexpr int OFF_F1  = OFF_F0 + BF32_STAGE;
constexpr int OFF_BH  = OFF_F1 + BF32_STAGE;
constexpr int OFF_BL  = OFF_BH + BB_PLANE;
constexpr int GSMEM   = OFF_BL + BB_PLANE;

template <int KTOT, int MTOT, int EPI, bool SPLIT>
__global__ __launch_bounds__(256, 2) void gemm_mma(
    const float* __restrict__ X0, const float* __restrict__ X1,
    const u16* __restrict__ Wh_g, const u16* __restrict__ Wl_g,
    const float* __restrict__ Bias, const float* __restrict__ Res,
    float* __restrict__ Out)
{
    extern __shared__ __align__(16) char sm[];
    const u32 sm0 = smem_u32(sm);

    const int img = blockIdx.z;
    const int p0  = blockIdx.x * 128;
    const int m0  = blockIdx.y * 128;
    const int tid = threadIdx.x;
    const int lane = tid & 31, wid = tid >> 5;
    const int wm = wid >> 2, wn = wid & 3;

    float acc[4][4][4];
#pragma unroll
    for (int i = 0; i < 4; i++)
#pragma unroll
        for (int j = 0; j < 4; j++)
#pragma unroll
            for (int q = 0; q < 4; q++) acc[i][j][q] = 0.f;

    constexpr int NCH = KTOT / KC;

    auto copyAB = [&](int c, int s) {
        const int kbase = c * KC;
        const float* Xc = X0;
        int kb = kbase;
        if (SPLIT && kbase >= 128) { Xc = X1; kb = kbase - 128; }
        const size_t bbase = ((size_t)img * (SPLIT ? 128 : KTOT) + kb) * NPIX + p0;
        const u32 fdst = sm0 + (s ? OFF_F1 : OFF_F0);
#pragma unroll
        for (int i = 0; i < 4; i++) {
            int idx = tid + i * 256;
            int row = idx >> 5, seg = idx & 31;
            cpasync16(fdst + row * BF32_PITCH + seg * 16,
                      Xc + bbase + (size_t)row * NPIX + seg * 4);
        }
        const size_t abase = (size_t)m0 * KTOT + kbase;
        const u32 adst = sm0 + (s ? OFF_A1 : OFF_A0);
#pragma unroll
        for (int i = 0; i < 4; i++) {
            int idx = tid + i * 256;
            int plane = idx >> 9, rem = idx & 511;
            int row = rem >> 2, seg = rem & 3;
            const u16* src = (plane ? Wl_g : Wh_g) + abase + (size_t)row * KTOT + seg * 8;
            cpasync16(adst + plane * A_PLANE_B + row * A_PITCH_B + seg * 16, src);
        }
    };

    const int lr  = lane & 7;
    const int lth = (lane >> 3) & 1;
    const int ltv = lane >> 4;
    const u32 a_row = (u32)(wm * 64 + lth * 8 + lr);

    copyAB(0, 0); cp_commit();

#pragma unroll 1
    for (int c = 0; c < NCH; c++) {
        const int s = c & 1;
        __syncthreads();
        if (c + 1 < NCH) {
            copyAB(c + 1, s ^ 1); cp_commit();
            asm volatile("cp.async.wait_group 1;" ::: "memory");
        } else {
            asm volatile("cp.async.wait_group 0;" ::: "memory");
        }
        __syncthreads();

        {
            const char* fsrc = sm + (s ? OFF_F1 : OFF_F0);
#pragma unroll
            for (int i = 0; i < 8; i++) {
                int p = tid + i * 256;
                int row = p >> 6, cp2 = p & 63;
                float2 v = *reinterpret_cast<const float2*>(fsrc + row * BF32_PITCH + cp2 * 8);
                u32 hi, lo;
                split_pack(v.x, v.y, hi, lo);
                *reinterpret_cast<u32*>(sm + OFF_BH + row * BB_PITCH + cp2 * 4) = hi;
                *reinterpret_cast<u32*>(sm + OFF_BL + row * BB_PITCH + cp2 * 4) = lo;
            }
        }
        __syncthreads();

        const u32 ah = sm0 + (s ? OFF_A1 : OFF_A0);
        const u32 al = ah + A_PLANE_B;
        const u32 bh = sm0 + OFF_BH, bl = sm0 + OFF_BL;

#pragma unroll
        for (int kk = 0; kk < KC / 16; kk++) {
            u32 af[4][4];
            u32 bfh[4][2], bfl[4][2];
            const u32 a_off = a_row * A_PITCH_B + kk * 32 + ltv * 16;
            const u32 b_off = (u32)(kk * 16 + lth * 8 + lr) * BB_PITCH + wn * 64 + ltv * 16;
#pragma unroll
            for (int mf = 0; mf < 4; mf++)
                ldm_x4(af[mf], ah + a_off + mf * 16 * A_PITCH_B);
#pragma unroll
            for (int nh = 0; nh < 2; nh++) {
                u32 r[4];
                ldm_x4t(r, bh + b_off + nh * 32);
                bfh[nh * 2][0] = r[0]; bfh[nh * 2][1] = r[1];
                bfh[nh * 2 + 1][0] = r[2]; bfh[nh * 2 + 1][1] = r[3];
            }
#pragma unroll
            for (int mf = 0; mf < 4; mf++)
#pragma unroll
                for (int nf = 0; nf < 4; nf++)
                    mma_bf16(acc[mf][nf], af[mf], bfh[nf]);
#pragma unroll
            for (int nh = 0; nh < 2; nh++) {
                u32 r[4];
                ldm_x4t(r, bl + b_off + nh * 32);
                bfl[nh * 2][0] = r[0]; bfl[nh * 2][1] = r[1];
                bfl[nh * 2 + 1][0] = r[2]; bfl[nh * 2 + 1][1] = r[3];
            }
#pragma unroll
            for (int mf = 0; mf < 4; mf++)
#pragma unroll
                for (int nf = 0; nf < 4; nf++)
                    mma_bf16(acc[mf][nf], af[mf], bfl[nf]);
#pragma unroll
            for (int mf = 0; mf < 4; mf++)
                ldm_x4(af[mf], al + a_off + mf * 16 * A_PITCH_B);
#pragma unroll
            for (int mf = 0; mf < 4; mf++)
#pragma unroll
                for (int nf = 0; nf < 4; nf++)
                    mma_bf16(acc[mf][nf], af[mf], bfh[nf]);
        }
    }

    const int g = lane >> 2, tg = lane & 3;
#pragma unroll
    for (int mf = 0; mf < 4; mf++) {
#pragma unroll
        for (int half = 0; half < 2; half++) {
            const int m = m0 + wm * 64 + mf * 16 + half * 8 + g;
            const float bias = Bias ? Bias[m] : 0.f;
            const size_t rowb = ((size_t)img * MTOT + m) * NPIX;
            const float* resrow = (EPI == 2) ? &Res[((size_t)img * CDIM + m) * NPIX] : nullptr;
#pragma unroll
            for (int nf = 0; nf < 4; nf++) {
                const int px = p0 + wn * 32 + nf * 8 + 2 * tg;
                float v0 = acc[mf][nf][half * 2 + 0] + bias;
                float v1 = acc[mf][nf][half * 2 + 1] + bias;
                if (EPI == 1) { v0 = gelu_exact(v0); v1 = gelu_exact(v1); }
                if (EPI == 2) { v0 += resrow[px]; v1 += resrow[px + 1]; }
                *reinterpret_cast<float2*>(&Out[rowb + px]) = make_float2(v0, v1);
            }
        }
    }
}

// ================= fused GRU v2: resident-A, M=64 x N=128 tile =================
// A rows interleaved: row 2c = W_hidden[c], row 2c+1 = W_gate[c]. CTA owns 64
// weight rows (32 channels) x 128 pixels; iterates v=0..5, h in smem.
constexpr int GA2_PLANE = 64 * 272;              // 17408 per plane (full K=128)
constexpr int G2_OFF_F0 = 2 * GA2_PLANE;         // 34816
constexpr int G2_OFF_F1 = G2_OFF_F0 + 32 * 528;  // 51712
constexpr int G2_OFF_BH = G2_OFF_F1 + 32 * 528;  // 68608
constexpr int G2_OFF_BL = G2_OFF_BH + 32 * 272;  // 77312
constexpr int G2_OFF_H  = G2_OFF_BL + 32 * 272;  // 86016
constexpr int GSMEM_G2  = G2_OFF_H + 32 * 128 * 4; // 102400

__global__ __launch_bounds__(256, 2) void gru_fused2(
    const float* __restrict__ X, const u16* __restrict__ Wh_g,
    const u16* __restrict__ Wl_g, float* __restrict__ Out)
{
    extern __shared__ __align__(16) char sm[];
    const u32 sm0 = smem_u32(sm);
    const int b  = blockIdx.z;
    const int p0 = blockIdx.x * 128;
    const int my = blockIdx.y;             // m-tile: weight rows [my*64, my*64+64)
    const int m0 = my * 64;
    const int tid = threadIdx.x;
    const int lane = tid & 31, wid = tid >> 5;
    const int wm = wid >> 2, wn = wid & 3;  // 2 m-warps x 4 n-warps
    const int lr = lane & 7, lth = (lane >> 3) & 1, ltv = lane >> 4;
    const int g = lane >> 2, tg = lane & 3;
    const u32 a_row = (u32)(wm * 32 + lth * 8 + lr);

    // zero h state (32 ch x 128 px fp32)
    for (int i = tid; i < 32 * 128 / 4; i += 256)
        reinterpret_cast<float4*>(sm + G2_OFF_H)[i] = make_float4(0.f, 0.f, 0.f, 0.f);

    float acc[2][4][4];
#pragma unroll
    for (int i = 0; i < 2; i++)
#pragma unroll
        for (int j = 0; j < 4; j++)
#pragma unroll
            for (int q = 0; q < 4; q++) acc[i][j][q] = 0.f;

    // resident A: 64 rows x 128 k, hi+lo
    {
#pragma unroll
        for (int i = 0; i < 8; i++) {
            int idx = tid + i * 256;              // 0..2047
            int plane = idx >> 10, rem = idx & 1023;
            int row = rem >> 4, seg = rem & 15;   // 64 rows x 16 segs(16B)
            const u16* src = (plane ? Wl_g : Wh_g) + (size_t)(m0 + row) * 128 + seg * 8;
            cpasync16(sm0 + plane * GA2_PLANE + row * 272 + seg * 16, src);
        }
        cp_commit();
    }

    auto copyB = [&](int it2, int s) {
        int v = it2 >> 2, ch = it2 & 3;
        const size_t bbase = ((size_t)(b * NV + v) * 128 + ch * 32) * NPIX + p0;
        const u32 fdst = sm0 + (s ? G2_OFF_F1 : G2_OFF_F0);
#pragma unroll
        for (int i = 0; i < 4; i++) {
            int idx = tid + i * 256;
            int row = idx >> 5, seg = idx & 31;   // 32 rows x 32 segs(16B)
            cpasync16(fdst + row * 528 + seg * 16,
                      X + bbase + (size_t)row * NPIX + seg * 4);
        }
    };

    copyB(0, 0); cp_commit();
    copyB(1, 1); cp_commit();

#pragma unroll 1
    for (int it = 0; it < 4 * NV; it++) {
        const int s = it & 1;
        if (it + 1 < 4 * NV) {
            asm volatile("cp.async.wait_group 1;" ::: "memory");  // F(it) landed
        } else {
            asm volatile("cp.async.wait_group 0;" ::: "memory");
        }
        __syncthreads();   // prior MMA reads of BH/BL done; F(it) visible

        // convert F(s) -> BH/BL
        {
            const char* fsrc = sm + (s ? G2_OFF_F1 : G2_OFF_F0);
#pragma unroll
            for (int i = 0; i < 8; i++) {
                int p = tid + i * 256;            // 2048 pairs: 32 rows x 64
                int row = p >> 6, cp2 = p & 63;
                float2 v = *reinterpret_cast<const float2*>(fsrc + row * 528 + cp2 * 8);
                u32 hi, lo;
                split_pack(v.x, v.y, hi, lo);
                *reinterpret_cast<u32*>(sm + G2_OFF_BH + row * 272 + cp2 * 4) = hi;
                *reinterpret_cast<u32*>(sm + G2_OFF_BL + row * 272 + cp2 * 4) = lo;
            }
        }
        __syncthreads();   // BH/BL ready; F(s) fully consumed

        if (it + 2 < 4 * NV) { copyB(it + 2, s); cp_commit(); }

        const u32 ah = sm0, al = sm0 + GA2_PLANE;
        const u32 bh = sm0 + G2_OFF_BH, bl = sm0 + G2_OFF_BL;
        const int ch = it & 3;
#pragma unroll
        for (int kk = 0; kk < 2; kk++) {
            u32 af[2][4];
            u32 bfh[4][2], bfl[4][2];
            const u32 a_off = a_row * 272 + (ch * 32 + kk * 16) * 2 + ltv * 16;
            const u32 b_off = (u32)(kk * 16 + lth * 8 + lr) * 272 + wn * 64 + ltv * 16;
#pragma unroll
            for (int mf = 0; mf < 2; mf++)
                ldm_x4(af[mf], ah + a_off + mf * 16 * 272);
#pragma unroll
            for (int nh = 0; nh < 2; nh++) {
                u32 r[4];
                ldm_x4t(r, bh + b_off + nh * 32);
                bfh[nh * 2][0] = r[0]; bfh[nh * 2][1] = r[1];
                bfh[nh * 2 + 1][0] = r[2]; bfh[nh * 2 + 1][1] = r[3];
            }
#pragma unroll
            for (int mf = 0; mf < 2; mf++)
#pragma unroll
                for (int nf = 0; nf < 4; nf++)
                    mma_bf16(acc[mf][nf], af[mf], bfh[nf]);
#pragma unroll
            for (int nh = 0; nh < 2; nh++) {
                u32 r[4];
                ldm_x4t(r, bl + b_off + nh * 32);
                bfl[nh * 2][0] = r[0]; bfl[nh * 2][1] = r[1];
                bfl[nh * 2 + 1][0] = r[2]; bfl[nh * 2 + 1][1] = r[3];
            }
#pragma unroll
            for (int mf = 0; mf < 2; mf++)
#pragma unroll
                for (int nf = 0; nf < 4; nf++)
                    mma_bf16(acc[mf][nf], af[mf], bfl[nf]);
#pragma unroll
            for (int mf = 0; mf < 2; mf++)
                ldm_x4(af[mf], al + a_off + mf * 16 * 272);
#pragma unroll
            for (int mf = 0; mf < 2; mf++)
#pragma unroll
                for (int nf = 0; nf < 4; nf++)
                    mma_bf16(acc[mf][nf], af[mf], bfh[nf]);
        }

        // end of view: scan epilogue (R8-verified shfl mapping, wm stride 32)
        if ((it & 3) == 3) {
            const int v = it >> 2;
#pragma unroll
            for (int mf = 0; mf < 2; mf++) {
#pragma unroll
                for (int nf = 0; nf < 4; nf++) {
#pragma unroll
                    for (int half = 0; half < 2; half++) {
                        float a0 = acc[mf][nf][half * 2 + 0];
                        float a1 = acc[mf][nf][half * 2 + 1];
                        float b0 = __shfl_xor_sync(0xffffffffu, a0, 4);
                        float b1 = __shfl_xor_sync(0xffffffffu, a1, 4);
                        if (!(g & 1)) {   // hidden-parity lanes own channel c
                            int row = wm * 32 + mf * 16 + half * 8 + g;
                            int cl = row >> 1;
                            int pxl = wn * 32 + nf * 8 + 2 * tg;
                            float2* hp = reinterpret_cast<float2*>(
                                sm + G2_OFF_H + (cl * 128 + pxl) * 4);
                            float2 h = *hp;
                            float z0 = 1.f / (1.f + expf(-b0));
                            float ht0 = (a0 >= 0.f) ? (a0 + 0.5f) : (1.f / (1.f + expf(-a0)));
                            h.x = (1.f - z0) * h.x + z0 * ht0;
                            float z1 = 1.f / (1.f + expf(-b1));
                            float ht1 = (a1 >= 0.f) ? (a1 + 0.5f) : (1.f / (1.f + expf(-a1)));
                            h.y = (1.f - z1) * h.y + z1 * ht1;
                            *hp = h;
                            *reinterpret_cast<float2*>(
                                &Out[((size_t)(b * NV + v) * 128 + my * 32 + cl) * NPIX
                                     + p0 + pxl]) = h;
                        }
                        acc[mf][nf][half * 2 + 0] = 0.f;
                        acc[mf][nf][half * 2 + 1] = 0.f;
                    }
                }
            }
        }
    }
}

// ---------------- weight prep (GRU rows interleaved) ----------------
__global__ void prep_w_all(
    const float* __restrict__ w1, const float* __restrict__ w2,
    const float* __restrict__ wg, const float* __restrict__ wgb,
    const float* __restrict__ wup,
    u16* __restrict__ w1h, u16* __restrict__ w1l,
    u16* __restrict__ w2h, u16* __restrict__ w2l,
    u16* __restrict__ wgh, u16* __restrict__ wgl,
    u16* __restrict__ wgbh, u16* __restrict__ wgbl,
    u16* __restrict__ wuph, u16* __restrict__ wupl)
{
    int i = blockIdx.x * 256 + threadIdx.x;
    float v; u16 *dh, *dl; int off;
    if      (i < 32768)  { off = i;          v = w1[off];  dh = w1h;  dl = w1l; }
    else if (i < 49152)  { off = i - 32768;  v = w2[off];  dh = w2h;  dl = w2l; }
    else if (i < 81920)  { off = i - 49152;
        int r = off >> 7, k = off & 127;
        int sr = (r & 1) ? 128 + (r >> 1) : (r >> 1);
        v = wg[sr * 128 + k]; dh = wgh; dl = wgl; }
    else if (i < 114688) { off = i - 81920;
        int r = off >> 7, k = off & 127;
        int sr = (r & 1) ? 128 + (r >> 1) : (r >> 1);
        v = wgb[sr * 128 + k]; dh = wgbh; dl = wgbl; }
    else                 { off = i - 114688; v = wup[off]; dh = wuph; dl = wupl; }
    float hf = __bfloat162float(__float2bfloat16(v));
    dh[off] = (u16)(__float_as_uint(hf) >> 16);
    dl[off] = (u16)(__float_as_uint(__bfloat162float(__float2bfloat16(v - hf))) >> 16);
}

// ---------------- depthwise 3x3 + bias + GELU ----------------
__global__ __launch_bounds__(256) void dw3x3(
    const float* __restrict__ in, const float* __restrict__ wd,
    const float* __restrict__ bd, float* __restrict__ out)
{
    int c = blockIdx.y, img = blockIdx.z;
    int pix = blockIdx.x * 256 + threadIdx.x;
    int h = pix >> 7, w = pix & 127;
    const float* p = in + ((size_t)img * CDIM + c) * NPIX;
    float s = bd[c];
#pragma unroll
    for (int ky = 0; ky < 3; ky++) {
        int hh = h + ky - 1;
        if ((unsigned)hh >= 128u) continue;
#pragma unroll
        for (int kx = 0; kx < 3; kx++) {
            int ww = w + kx - 1;
            if ((unsigned)ww >= 128u) continue;
            s = fmaf(wd[c * 9 + ky * 3 + kx], p[hh * WW + ww], s);
        }
    }
    out[((size_t)img * CDIM + c) * NPIX + pix] = gelu_exact(s);
}

// ---------------- alpha: 3x3 conv C->1 ----------------
__global__ __launch_bounds__(256) void alpha_conv(
    const float* __restrict__ g2, const float* __restrict__ aw,
    const float* __restrict__ ab, float* __restrict__ alpha)
{
    __shared__ float w[1152];
    for (int i = threadIdx.x; i < 1152; i += 256) w[i] = aw[i];
    __syncthreads();
    int img = blockIdx.z;
    int pix = blockIdx.x * 256 + threadIdx.x;
    int h = pix >> 7, x = pix & 127;
    float s = ab[0];
    const float* base = g2 + (size_t)img * CDIM * NPIX;
    for (int c = 0; c < CDIM; c++) {
        const float* p  = base + (size_t)c * NPIX;
        const float* wc = w + c * 9;
#pragma unroll
        for (int ky = 0; ky < 3; ky++) {
            int hh = h + ky - 1;
            if ((unsigned)hh >= 128u) continue;
#pragma unroll
            for (int kx = 0; kx < 3; kx++) {
                int ww = x + kx - 1;
                if ((unsigned)ww >= 128u) continue;
                s = fmaf(wc[ky * 3 + kx], p[hh * WW + ww], s);
            }
        }
    }
    alpha[(size_t)img * NPIX + pix] = s;
}

// ---------------- softmax over V + weighted pool ----------------
__global__ __launch_bounds__(256) void pool_k(
    const float* __restrict__ g2, const float* __restrict__ alpha, float* __restrict__ out)
{
    int b = blockIdx.z;
    int pix = blockIdx.x * 256 + threadIdx.x;
    float a[NV];
    float mx = -1e30f;
#pragma unroll
    for (int v = 0; v < NV; v++) {
        a[v] = alpha[(size_t)(b * NV + v) * NPIX + pix];
        mx = fmaxf(mx, a[v]);
    }
    float sum = 0.f;
#pragma unroll
    for (int v = 0; v < NV; v++) { a[v] = expf(a[v] - mx); sum += a[v]; }
    float inv = 1.f / sum;
#pragma unroll
    for (int v = 0; v < NV; v++) a[v] *= inv;
    for (int c = 0; c < CDIM; c++) {
        float s = 0.f;
#pragma unroll
        for (int v = 0; v < NV; v++)
            s = fmaf(a[v], g2[(((size_t)(b * NV + v)) * CDIM + c) * NPIX + pix], s);
        out[((size_t)b * CDIM + c) * NPIX + pix] = s;
    }
}

// ---------------- pixel-shuffle(4) + 3x3 conv 8->3 (512->512 resize = identity) ----------------
__global__ __launch_bounds__(256) void outc_k(
    const float* __restrict__ u, const float* __restrict__ wt,
    const float* __restrict__ bs, float* __restrict__ out)
{
    __shared__ float w[216];
    if (threadIdx.x < 216) w[threadIdx.x] = wt[threadIdx.x];
    __syncthreads();
    int b = blockIdx.z, co = blockIdx.y;
    int idx = blockIdx.x * 256 + threadIdx.x;
    int y = idx >> 9, x = idx & 511;
    float s = bs[co];
    const float* ub = u + (size_t)b * CDIM * NPIX;
#pragma unroll
    for (int ky = 0; ky < 3; ky++) {
        int yy = y + ky - 1;
        if ((unsigned)yy >= 512u) continue;
        int sy = yy & 3, hy = yy >> 2;
#pragma unroll
        for (int kx = 0; kx < 3; kx++) {
            int xx = x + kx - 1;
            if ((unsigned)xx >= 512u) continue;
            int sx = xx & 3, hx = xx >> 2;
            const float* up = ub + (size_t)(sy * 4 + sx) * NPIX + hy * WW + hx;
#pragma unroll
            for (int ci = 0; ci < 8; ci++)
                s = fmaf(w[(co * 8 + ci) * 9 + ky * 3 + kx], up[(size_t)ci * 16 * NPIX], s);
        }
    }
    out[((size_t)b * 3 + co) * (512 * 512) + idx] = s;
}

// ---------------- launch ----------------
extern "C" void kernel_launch(void* const* d_in, const int* in_sizes, int n_in,
                              void* d_out, int out_size)
{
    const float* feats     = (const float*)d_in[0];
    const float* prj       = (const float*)d_in[1];
    const float* merge_w1  = (const float*)d_in[2];
    const float* merge_b1  = (const float*)d_in[3];
    const float* merge_wd  = (const float*)d_in[4];
    const float* merge_bd  = (const float*)d_in[5];
    const float* merge_w2  = (const float*)d_in[6];
    const float* merge_b2  = (const float*)d_in[7];
    const float* gru_w     = (const float*)d_in[8];
    const float* gru_bw    = (const float*)d_in[9];
    const float* alpha_w   = (const float*)d_in[10];
    const float* alpha_b   = (const float*)d_in[11];
    const float* up_w      = (const float*)d_in[12];
    const float* up_b      = (const float*)d_in[13];
    const float* outc_w    = (const float*)d_in[14];
    const float* outc_b    = (const float*)d_in[15];

    float *bufA, *bufB, *bufC, *alp, *pool, *u;
    u16 *wm1h, *wm1l, *wm2h, *wm2l, *wgh, *wgl, *wgbh, *wgbl, *wuph, *wupl;
    cudaGetSymbolAddress((void**)&bufA, g_bufA);
    cudaGetSymbolAddress((void**)&bufB, g_bufB);
    cudaGetSymbolAddress((void**)&bufC, g_bufC);
    cudaGetSymbolAddress((void**)&alp,  g_alp);
    cudaGetSymbolAddress((void**)&pool, g_pool);
    cudaGetSymbolAddress((void**)&u,    g_u);
    cudaGetSymbolAddress((void**)&wm1h, g_wm1h); cudaGetSymbolAddress((void**)&wm1l, g_wm1l);
    cudaGetSymbolAddress((void**)&wm2h, g_wm2h); cudaGetSymbolAddress((void**)&wm2l, g_wm2l);
    cudaGetSymbolAddress((void**)&wgh,  g_wgh);  cudaGetSymbolAddress((void**)&wgl,  g_wgl);
    cudaGetSymbolAddress((void**)&wgbh, g_wgbh); cudaGetSymbolAddress((void**)&wgbl, g_wgbl);
    cudaGetSymbolAddress((void**)&wuph, g_wuph); cudaGetSymbolAddress((void**)&wupl, g_wupl);

    cudaFuncSetAttribute(gemm_mma<256, 128, 1, true >, cudaFuncAttributeMaxDynamicSharedMemorySize, GSMEM);
    cudaFuncSetAttribute(gemm_mma<128, 128, 2, false>, cudaFuncAttributeMaxDynamicSharedMemorySize, GSMEM);
    cudaFuncSetAttribute(gemm_mma<128, 128, 0, false>, cudaFuncAttributeMaxDynamicSharedMemorySize, GSMEM);
    cudaFuncSetAttribute(gru_fused2, cudaFuncAttributeMaxDynamicSharedMemorySize, GSMEM_G2);
    cudaFuncSetAttribute(gemm_mma<256, 128, 1, true >, cudaFuncAttributePreferredSharedMemoryCarveout, 100);
    cudaFuncSetAttribute(gemm_mma<128, 128, 2, false>, cudaFuncAttributePreferredSharedMemoryCarveout, 100);
    cudaFuncSetAttribute(gemm_mma<128, 128, 0, false>, cudaFuncAttributePreferredSharedMemoryCarveout, 100);
    cudaFuncSetAttribute(gru_fused2, cudaFuncAttributePreferredSharedMemoryCarveout, 100);

    prep_w_all<<<512, 256>>>(merge_w1, merge_w2, gru_w, gru_bw, up_w,
                             wm1h, wm1l, wm2h, wm2l, wgh, wgl, wgbh, wgbl, wuph, wupl);

    // merge1: 1x1 (2C->C) + GELU
    gemm_mma<256, 128, 1, true ><<<dim3(128, 1, BVI), 256, GSMEM>>>(
        feats, prj, wm1h, wm1l, merge_b1, nullptr, bufA);
    // depthwise 3x3 + GELU
    dw3x3<<<dim3(64, CDIM, BVI), 256>>>(bufA, merge_wd, merge_bd, bufB);
    // merge2: 1x1 (C->C) + bias + residual
    gemm_mma<128, 128, 2, false><<<dim3(128, 1, BVI), 256, GSMEM>>>(
        bufB, nullptr, wm2h, wm2l, merge_b2, feats, bufC);
    // fused fwd GRU (linear + scan)
    gru_fused2<<<dim3(NPIX / 128, 4, NB), 256, GSMEM_G2>>>(bufC, wgh, wgl, bufA);
    // fused bwd GRU (H-flips cancel -> forward scan)
    gru_fused2<<<dim3(NPIX / 128, 4, NB), 256, GSMEM_G2>>>(bufA, wgbh, wgbl, bufB);
    // alpha conv + softmax pool
    alpha_conv<<<dim3(64, 1, BVI), 256>>>(bufB, alpha_w, alpha_b, alp);
    pool_k<<<dim3(64, 1, NB), 256>>>(bufB, alp, pool);
    // up 1x1 conv
    gemm_mma<128, 128, 0, false><<<dim3(128, 1, NB), 256, GSMEM>>>(
        pool, nullptr, wuph, wupl, up_b, nullptr, u);
    // pixel shuffle + outc 3x3
    outc_k<<<dim3(1024, 3, NB), 256>>>(u, outc_w, outc_b, (float*)d_out);
}

// round 11
// speedup vs baseline: 1.1160x; 1.0876x over previous
#include <cuda_runtime.h>
#include <cuda_bf16.h>
#include <math.h>
#include <stdint.h>

#define NPIX 16384
#define CDIM 128
#define NB 2
#define NV 6
#define BVI 12
#define WW 128

typedef uint16_t u16;
typedef uint32_t u32;

// ---------------- scratch ----------------
__device__ float g_bufA[(size_t)BVI * CDIM * NPIX];
__device__ float g_bufB[(size_t)BVI * CDIM * NPIX];
__device__ float g_bufC[(size_t)BVI * CDIM * NPIX];
__device__ float g_hg  [(size_t)BVI * 2 * CDIM * NPIX];
__device__ float g_alp [(size_t)BVI * NPIX];
__device__ float g_pool[(size_t)NB * CDIM * NPIX];
__device__ float g_u   [(size_t)NB * CDIM * NPIX];
// weight hi/lo planes (k-major rows)
__device__ __align__(16) u16 g_wm1h[128 * 256], g_wm1l[128 * 256];
__device__ __align__(16) u16 g_wm2h[128 * 128], g_wm2l[128 * 128];
__device__ __align__(16) u16 g_wgh [256 * 128], g_wgl [256 * 128];
__device__ __align__(16) u16 g_wgbh[256 * 128], g_wgbl[256 * 128];
__device__ __align__(16) u16 g_wuph[128 * 128], g_wupl[128 * 128];

__device__ __forceinline__ float gelu_exact(float x) {
    return 0.5f * x * (1.0f + erff(x * 0.70710678118654752f));
}
__device__ __forceinline__ u32 smem_u32(const void* p) {
    return (u32)__cvta_generic_to_shared(p);
}
__device__ __forceinline__ void split_pack(float v0, float v1, u32& hi, u32& lo) {
    asm("cvt.rn.bf16x2.f32 %0, %1, %2;" : "=r"(hi) : "f"(v1), "f"(v0));
    float r0 = v0 - __uint_as_float(hi << 16);
    float r1 = v1 - __uint_as_float(hi & 0xffff0000u);
    asm("cvt.rn.bf16x2.f32 %0, %1, %2;" : "=r"(lo) : "f"(r1), "f"(r0));
}
__device__ __forceinline__ void ldm_x4(u32* r, u32 addr) {
    asm volatile("ldmatrix.sync.aligned.m8n8.x4.shared.b16 {%0,%1,%2,%3}, [%4];"
                 : "=r"(r[0]), "=r"(r[1]), "=r"(r[2]), "=r"(r[3]) : "r"(addr));
}
__device__ __forceinline__ void ldm_x4t(u32* r, u32 addr) {
    asm volatile("ldmatrix.sync.aligned.m8n8.x4.trans.shared.b16 {%0,%1,%2,%3}, [%4];"
                 : "=r"(r[0]), "=r"(r[1]), "=r"(r[2]), "=r"(r[3]) : "r"(addr));
}
__device__ __forceinline__ void mma_bf16(float* d, const u32* a, const u32* b) {
    asm volatile(
        "mma.sync.aligned.m16n8k16.row.col.f32.bf16.bf16.f32 "
        "{%0,%1,%2,%3}, {%4,%5,%6,%7}, {%8,%9}, {%0,%1,%2,%3};"
        : "+f"(d[0]), "+f"(d[1]), "+f"(d[2]), "+f"(d[3])
        : "r"(a[0]), "r"(a[1]), "r"(a[2]), "r"(a[3]), "r"(b[0]), "r"(b[1]));
}
__device__ __forceinline__ void cpasync16(u32 dst, const void* src) {
    asm volatile("cp.async.cg.shared.global [%0], [%1], 16;" :: "r"(dst), "l"(src));
}
__device__ __forceinline__ void cp_commit() {
    asm volatile("cp.async.commit_group;" ::: "memory");
}

// ================= GEMM v2b: register-staged B, hazard-free ordering =================
constexpr int KC = 32;
constexpr int A_PITCH_B = 80;
constexpr int A_PLANE_B = 128 * A_PITCH_B;       // 10240
constexpr int A_STAGE_B = 2 * A_PLANE_B;         // 20480 (hi+lo)
constexpr int BB_PITCH = 272;
constexpr int BB_PLANE = KC * BB_PITCH;          // 8704
constexpr int BB_STAGE = 2 * BB_PLANE;           // hi+lo 17408
constexpr int OFF_B0 = 2 * A_STAGE_B;            // 40960
constexpr int GSMEM  = OFF_B0 + 2 * BB_STAGE;    // 75776

template <int KTOT, int MTOT, int EPI, bool SPLIT>
__global__ __launch_bounds__(256, 2) void gemm_mma(
    const float* __restrict__ X0, const float* __restrict__ X1,
    const u16* __restrict__ Wh_g, const u16* __restrict__ Wl_g,
    const float* __restrict__ Bias, const float* __restrict__ Res,
    float* __restrict__ Out)
{
    extern __shared__ __align__(16) char sm[];
    const u32 sm0 = smem_u32(sm);

    const int img = blockIdx.z;
    const int p0  = blockIdx.x * 128;
    const int m0  = blockIdx.y * 128;
    const int tid = threadIdx.x;
    const int lane = tid & 31, wid = tid >> 5;
    const int wm = wid >> 2, wn = wid & 3;

    float acc[4][4][4];
#pragma unroll
    for (int i = 0; i < 4; i++)
#pragma unroll
        for (int j = 0; j < 4; j++)
#pragma unroll
            for (int q = 0; q < 4; q++) acc[i][j][q] = 0.f;

    constexpr int NCH = KTOT / KC;

    float4 breg[2][4];

    auto ldgB = [&](int c, int buf) {
        const int kbase = c * KC;
        const float* Xc = X0;
        int kb = kbase;
        if (SPLIT && kbase >= 128) { Xc = X1; kb = kbase - 128; }
        const size_t bbase = ((size_t)img * (SPLIT ? 128 : KTOT) + kb) * NPIX + p0;
#pragma unroll
        for (int i = 0; i < 4; i++) {
            int idx = tid + i * 256;
            int row = idx >> 5, seg = idx & 31;
            breg[buf][i] = *reinterpret_cast<const float4*>(
                Xc + bbase + (size_t)row * NPIX + seg * 4);
        }
    };
    auto copyA = [&](int c, int s) {
        const size_t abase = (size_t)m0 * KTOT + c * KC;
        const u32 adst = sm0 + s * A_STAGE_B;
#pragma unroll
        for (int i = 0; i < 4; i++) {
            int idx = tid + i * 256;
            int plane = idx >> 9, rem = idx & 511;
            int row = rem >> 2, seg = rem & 3;
            const u16* src = (plane ? Wl_g : Wh_g) + abase + (size_t)row * KTOT + seg * 8;
            cpasync16(adst + plane * A_PLANE_B + row * A_PITCH_B + seg * 16, src);
        }
    };

    const int lr  = lane & 7;
    const int lth = (lane >> 3) & 1;
    const int ltv = lane >> 4;
    const u32 a_row = (u32)(wm * 64 + lth * 8 + lr);

    ldgB(0, 0);
    copyA(0, 0); cp_commit();

#pragma unroll 1
    for (int c = 0; c < NCH; c++) {
        const int s = c & 1;
        if (c + 1 < NCH) ldgB(c + 1, s ^ 1);   // registers only; lands during MMA(c)

        // convert breg[s] -> bf16 planes, stage s
        // (stage s last read by MMA(c-2), fenced by sync of iteration c-1)
        {
            const u32 bhoff = OFF_B0 + s * BB_STAGE;
#pragma unroll
            for (int i = 0; i < 4; i++) {
                int idx = tid + i * 256;
                int row = idx >> 5, seg = idx & 31;
                float4 v = breg[s][i];
                u32 h0, l0, h1, l1;
                split_pack(v.x, v.y, h0, l0);
                split_pack(v.z, v.w, h1, l1);
                u32 off = (u32)row * BB_PITCH + seg * 8;
                *reinterpret_cast<uint2*>(sm + bhoff + off) = make_uint2(h0, h1);
                *reinterpret_cast<uint2*>(sm + bhoff + BB_PLANE + off) = make_uint2(l0, l1);
            }
        }
        asm volatile("cp.async.wait_group 0;" ::: "memory");   // A(c) landed
        __syncthreads();   // all MMA(c-1) reads of stage s^1 done; B(s)/A(s) visible

        if (c + 1 < NCH) { copyA(c + 1, s ^ 1); cp_commit(); } // safe post-sync

        const u32 ah = sm0 + s * A_STAGE_B;
        const u32 al = ah + A_PLANE_B;
        const u32 bh = sm0 + OFF_B0 + s * BB_STAGE;
        const u32 bl = bh + BB_PLANE;

#pragma unroll
        for (int kk = 0; kk < KC / 16; kk++) {
            u32 af[4][4];
            u32 bfh[4][2], bfl[4][2];
            const u32 a_off = a_row * A_PITCH_B + kk * 32 + ltv * 16;
            const u32 b_off = (u32)(kk * 16 + lth * 8 + lr) * BB_PITCH + wn * 64 + ltv * 16;
#pragma unroll
            for (int mf = 0; mf < 4; mf++)
                ldm_x4(af[mf], ah + a_off + mf * 16 * A_PITCH_B);
#pragma unroll
            for (int nh = 0; nh < 2; nh++) {
                u32 r[4];
                ldm_x4t(r, bh + b_off + nh * 32);
                bfh[nh * 2][0] = r[0]; bfh[nh * 2][1] = r[1];
                bfh[nh * 2 + 1][0] = r[2]; bfh[nh * 2 + 1][1] = r[3];
            }
#pragma unroll
            for (int mf = 0; mf < 4; mf++)
#pragma unroll
                for (int nf = 0; nf < 4; nf++)
                    mma_bf16(acc[mf][nf], af[mf], bfh[nf]);
#pragma unroll
            for (int nh = 0; nh < 2; nh++) {
                u32 r[4];
                ldm_x4t(r, bl + b_off + nh * 32);
                bfl[nh * 2][0] = r[0]; bfl[nh * 2][1] = r[1];
                bfl[nh * 2 + 1][0] = r[2]; bfl[nh * 2 + 1][1] = r[3];
            }
#pragma unroll
            for (int mf = 0; mf < 4; mf++)
#pragma unroll
                for (int nf = 0; nf < 4; nf++)
                    mma_bf16(acc[mf][nf], af[mf], bfl[nf]);
#pragma unroll
            for (int mf = 0; mf < 4; mf++)
                ldm_x4(af[mf], al + a_off + mf * 16 * A_PITCH_B);
#pragma unroll
            for (int mf = 0; mf < 4; mf++)
#pragma unroll
                for (int nf = 0; nf < 4; nf++)
                    mma_bf16(acc[mf][nf], af[mf], bfh[nf]);
        }
    }

    const int g = lane >> 2, tg = lane & 3;
#pragma unroll
    for (int mf = 0; mf < 4; mf++) {
#pragma unroll
        for (int half = 0; half < 2; half++) {
            const int m = m0 + wm * 64 + mf * 16 + half * 8 + g;
            const float bias = Bias ? Bias[m] : 0.f;
            const size_t rowb = ((size_t)img * MTOT + m) * NPIX;
            const float* resrow = (EPI == 2) ? &Res[((size_t)img * CDIM + m) * NPIX] : nullptr;
#pragma unroll
            for (int nf = 0; nf < 4; nf++) {
                const int px = p0 + wn * 32 + nf * 8 + 2 * tg;
                float v0 = acc[mf][nf][half * 2 + 0] + bias;
                float v1 = acc[mf][nf][half * 2 + 1] + bias;
                if (EPI == 1) { v0 = gelu_exact(v0); v1 = gelu_exact(v1); }
                if (EPI == 2) { v0 += resrow[px]; v1 += resrow[px + 1]; }
                *reinterpret_cast<float2*>(&Out[rowb + px]) = make_float2(v0, v1);
            }
        }
    }
}

// ---------------- fused weight prep ----------------
__global__ void prep_w_all(
    const float* __restrict__ w1, const float* __restrict__ w2,
    const float* __restrict__ wg, const float* __restrict__ wgb,
    const float* __restrict__ wup,
    u16* __restrict__ w1h, u16* __restrict__ w1l,
    u16* __restrict__ w2h, u16* __restrict__ w2l,
    u16* __restrict__ wgh, u16* __restrict__ wgl,
    u16* __restrict__ wgbh, u16* __restrict__ wgbl,
    u16* __restrict__ wuph, u16* __restrict__ wupl)
{
    int i = blockIdx.x * 256 + threadIdx.x;
    const float* src; u16 *dh, *dl; int off;
    if      (i < 32768)  { src = w1;  dh = w1h;  dl = w1l;  off = i; }
    else if (i < 49152)  { src = w2;  dh = w2h;  dl = w2l;  off = i - 32768; }
    else if (i < 81920)  { src = wg;  dh = wgh;  dl = wgl;  off = i - 49152; }
    else if (i < 114688) { src = wgb; dh = wgbh; dl = wgbl; off = i - 81920; }
    else                 { src = wup; dh = wuph; dl = wupl; off = i - 114688; }
    float v = src[off];
    float hf = __bfloat162float(__float2bfloat16(v));
    dh[off] = (u16)(__float_as_uint(hf) >> 16);
    dl[off] = (u16)(__float_as_uint(__bfloat162float(__float2bfloat16(v - hf))) >> 16);
}

// ---------------- depthwise 3x3 + bias + GELU ----------------
__global__ __launch_bounds__(256) void dw3x3(
    const float* __restrict__ in, const float* __restrict__ wd,
    const float* __restrict__ bd, float* __restrict__ out)
{
    int c = blockIdx.y, img = blockIdx.z;
    int pix = blockIdx.x * 256 + threadIdx.x;
    int h = pix >> 7, w = pix & 127;
    const float* p = in + ((size_t)img * CDIM + c) * NPIX;
    float s = bd[c];
#pragma unroll
    for (int ky = 0; ky < 3; ky++) {
        int hh = h + ky - 1;
        if ((unsigned)hh >= 128u) continue;
#pragma unroll
        for (int kx = 0; kx < 3; kx++) {
            int ww = w + kx - 1;
            if ((unsigned)ww >= 128u) continue;
            s = fmaf(wd[c * 9 + ky * 3 + kx], p[hh * WW + ww], s);
        }
    }
    out[((size_t)img * CDIM + c) * NPIX + pix] = gelu_exact(s);
}

// ---------------- minGRU scan over V (float4 vectorized) ----------------
__global__ __launch_bounds__(256) void gru_scan4(const float* __restrict__ hg, float* __restrict__ g)
{
    int c = blockIdx.y, b = blockIdx.z;
    int pix0 = (blockIdx.x * 256 + threadIdx.x) * 4;
    float4 h = make_float4(0.f, 0.f, 0.f, 0.f);
#pragma unroll
    for (int v = 0; v < NV; v++) {
        size_t base = (((size_t)(b * NV + v)) * 2 * CDIM + c) * NPIX + pix0;
        float4 hid = *reinterpret_cast<const float4*>(&hg[base]);
        float4 gt  = *reinterpret_cast<const float4*>(&hg[base + (size_t)CDIM * NPIX]);
        float z, ht;
        z = 1.f / (1.f + expf(-gt.x)); ht = (hid.x >= 0.f) ? (hid.x + 0.5f) : (1.f / (1.f + expf(-hid.x)));
        h.x = (1.f - z) * h.x + z * ht;
        z = 1.f / (1.f + expf(-gt.y)); ht = (hid.y >= 0.f) ? (hid.y + 0.5f) : (1.f / (1.f + expf(-hid.y)));
        h.y = (1.f - z) * h.y + z * ht;
        z = 1.f / (1.f + expf(-gt.z)); ht = (hid.z >= 0.f) ? (hid.z + 0.5f) : (1.f / (1.f + expf(-hid.z)));
        h.z = (1.f - z) * h.z + z * ht;
        z = 1.f / (1.f + expf(-gt.w)); ht = (hid.w >= 0.f) ? (hid.w + 0.5f) : (1.f / (1.f + expf(-hid.w)));
        h.w = (1.f - z) * h.w + z * ht;
        *reinterpret_cast<float4*>(&g[(((size_t)(b * NV + v)) * CDIM + c) * NPIX + pix0]) = h;
    }
}

// ---------------- alpha: 3x3 conv C->1 ----------------
__global__ __launch_bounds__(256) void alpha_conv(
    const float* __restrict__ g2, const float* __restrict__ aw,
    const float* __restrict__ ab, float* __restrict__ alpha)
{
    __shared__ float w[1152];
    for (int i = threadIdx.x; i < 1152; i += 256) w[i] = aw[i];
    __syncthreads();
    int img = blockIdx.z;
    int pix = blockIdx.x * 256 + threadIdx.x;
    int h = pix >> 7, x = pix & 127;
    float s = ab[0];
    const float* base = g2 + (size_t)img * CDIM * NPIX;
    for (int c = 0; c < CDIM; c++) {
        const float* p  = base + (size_t)c * NPIX;
        const float* wc = w + c * 9;
#pragma unroll
        for (int ky = 0; ky < 3; ky++) {
            int hh = h + ky - 1;
            if ((unsigned)hh >= 128u) continue;
#pragma unroll
            for (int kx = 0; kx < 3; kx++) {
                int ww = x + kx - 1;
                if ((unsigned)ww >= 128u) continue;
                s = fmaf(wc[ky * 3 + kx], p[hh * WW + ww], s);
            }
        }
    }
    alpha[(size_t)img * NPIX + pix] = s;
}

// ---------------- softmax over V + weighted pool (float4 vectorized) ----------------
__global__ __launch_bounds__(256) void pool_k4(
    const float* __restrict__ g2, const float* __restrict__ alpha, float* __restrict__ out)
{
    int b = blockIdx.z;
    int pix0 = (blockIdx.x * 256 + threadIdx.x) * 4;
    float4 a[NV];
    float4 mx = make_float4(-1e30f, -1e30f, -1e30f, -1e30f);
#pragma unroll
    for (int v = 0; v < NV; v++) {
        a[v] = *reinterpret_cast<const float4*>(&alpha[(size_t)(b * NV + v) * NPIX + pix0]);
        mx.x = fmaxf(mx.x, a[v].x); mx.y = fmaxf(mx.y, a[v].y);
        mx.z = fmaxf(mx.z, a[v].z); mx.w = fmaxf(mx.w, a[v].w);
    }
    float4 sum = make_float4(0.f, 0.f, 0.f, 0.f);
#pragma unroll
    for (int v = 0; v < NV; v++) {
        a[v].x = expf(a[v].x - mx.x); sum.x += a[v].x;
        a[v].y = expf(a[v].y - mx.y); sum.y += a[v].y;
        a[v].z = expf(a[v].z - mx.z); sum.z += a[v].z;
        a[v].w = expf(a[v].w - mx.w); sum.w += a[v].w;
    }
    float4 inv = make_float4(1.f / sum.x, 1.f / sum.y, 1.f / sum.z, 1.f / sum.w);
#pragma unroll
    for (int v = 0; v < NV; v++) {
        a[v].x *= inv.x; a[v].y *= inv.y; a[v].z *= inv.z; a[v].w *= inv.w;
    }
    for (int c = 0; c < CDIM; c++) {
        float4 s = make_float4(0.f, 0.f, 0.f, 0.f);
#pragma unroll
        for (int v = 0; v < NV; v++) {
            float4 gv = *reinterpret_cast<const float4*>(
                &g2[(((size_t)(b * NV + v)) * CDIM + c) * NPIX + pix0]);
            s.x = fmaf(a[v].x, gv.x, s.x);
            s.y = fmaf(a[v].y, gv.y, s.y);
            s.z = fmaf(a[v].z, gv.z, s.z);
            s.w = fmaf(a[v].w, gv.w, s.w);
        }
        *reinterpret_cast<float4*>(&out[((size_t)b * CDIM + c) * NPIX + pix0]) = s;
    }
}

// ---------------- pixel-shuffle(4) + 3x3 conv 8->3 (512->512 resize = identity) ----------------
__global__ __launch_bounds__(256) void outc_k(
    const float* __restrict__ u, const float* __restrict__ wt,
    const float* __restrict__ bs, float* __restrict__ out)
{
    __shared__ float w[216];
    if (threadIdx.x < 216) w[threadIdx.x] = wt[threadIdx.x];
    __syncthreads();
    int b = blockIdx.z, co = blockIdx.y;
    int idx = blockIdx.x * 256 + threadIdx.x;
    int y = idx >> 9, x = idx & 511;
    float s = bs[co];
    const float* ub = u + (size_t)b * CDIM * NPIX;
#pragma unroll
    for (int ky = 0; ky < 3; ky++) {
        int yy = y + ky - 1;
        if ((unsigned)yy >= 512u) continue;
        int sy = yy & 3, hy = yy >> 2;
#pragma unroll
        for (int kx = 0; kx < 3; kx++) {
            int xx = x + kx - 1;
            if ((unsigned)xx >= 512u) continue;
            int sx = xx & 3, hx = xx >> 2;
            const float* up = ub + (size_t)(sy * 4 + sx) * NPIX + hy * WW + hx;
#pragma unroll
            for (int ci = 0; ci < 8; ci++)
                s = fmaf(w[(co * 8 + ci) * 9 + ky * 3 + kx], up[(size_t)ci * 16 * NPIX], s);
        }
    }
    out[((size_t)b * 3 + co) * (512 * 512) + idx] = s;
}

// ---------------- launch ----------------
extern "C" void kernel_launch(void* const* d_in, const int* in_sizes, int n_in,
                              void* d_out, int out_size)
{
    const float* feats     = (const float*)d_in[0];
    const float* prj       = (const float*)d_in[1];
    const float* merge_w1  = (const float*)d_in[2];
    const float* merge_b1  = (const float*)d_in[3];
    const float* merge_wd  = (const float*)d_in[4];
    const float* merge_bd  = (const float*)d_in[5];
    const float* merge_w2  = (const float*)d_in[6];
    const float* merge_b2  = (const float*)d_in[7];
    const float* gru_w     = (const float*)d_in[8];
    const float* gru_bw    = (const float*)d_in[9];
    const float* alpha_w   = (const float*)d_in[10];
    const float* alpha_b   = (const float*)d_in[11];
    const float* up_w      = (const float*)d_in[12];
    const float* up_b      = (const float*)d_in[13];
    const float* outc_w    = (const float*)d_in[14];
    const float* outc_b    = (const float*)d_in[15];

    float *bufA, *bufB, *bufC, *hg, *alp, *pool, *u;
    u16 *wm1h, *wm1l, *wm2h, *wm2l, *wgh, *wgl, *wgbh, *wgbl, *wuph, *wupl;
    cudaGetSymbolAddress((void**)&bufA, g_bufA);
    cudaGetSymbolAddress((void**)&bufB, g_bufB);
    cudaGetSymbolAddress((void**)&bufC, g_bufC);
    cudaGetSymbolAddress((void**)&hg,   g_hg);
    cudaGetSymbolAddress((void**)&alp,  g_alp);
    cudaGetSymbolAddress((void**)&pool, g_pool);
    cudaGetSymbolAddress((void**)&u,    g_u);
    cudaGetSymbolAddress((void**)&wm1h, g_wm1h); cudaGetSymbolAddress((void**)&wm1l, g_wm1l);
    cudaGetSymbolAddress((void**)&wm2h, g_wm2h); cudaGetSymbolAddress((void**)&wm2l, g_wm2l);
    cudaGetSymbolAddress((void**)&wgh,  g_wgh);  cudaGetSymbolAddress((void**)&wgl,  g_wgl);
    cudaGetSymbolAddress((void**)&wgbh, g_wgbh); cudaGetSymbolAddress((void**)&wgbl, g_wgbl);
    cudaGetSymbolAddress((void**)&wuph, g_wuph); cudaGetSymbolAddress((void**)&wupl, g_wupl);

    cudaFuncSetAttribute(gemm_mma<256, 128, 1, true >, cudaFuncAttributeMaxDynamicSharedMemorySize, GSMEM);
    cudaFuncSetAttribute(gemm_mma<128, 128, 2, false>, cudaFuncAttributeMaxDynamicSharedMemorySize, GSMEM);
    cudaFuncSetAttribute(gemm_mma<128, 256, 0, false>, cudaFuncAttributeMaxDynamicSharedMemorySize, GSMEM);
    cudaFuncSetAttribute(gemm_mma<128, 128, 0, false>, cudaFuncAttributeMaxDynamicSharedMemorySize, GSMEM);

    prep_w_all<<<512, 256>>>(merge_w1, merge_w2, gru_w, gru_bw, up_w,
                             wm1h, wm1l, wm2h, wm2l, wgh, wgl, wgbh, wgbl, wuph, wupl);

    // merge1: 1x1 (2C->C) + GELU
    gemm_mma<256, 128, 1, true ><<<dim3(128, 1, BVI), 256, GSMEM>>>(
        feats, prj, wm1h, wm1l, merge_b1, nullptr, bufA);
    // depthwise 3x3 + GELU
    dw3x3<<<dim3(64, CDIM, BVI), 256>>>(bufA, merge_wd, merge_bd, bufB);
    // merge2: 1x1 (C->C) + bias + residual
    gemm_mma<128, 128, 2, false><<<dim3(128, 1, BVI), 256, GSMEM>>>(
        bufB, nullptr, wm2h, wm2l, merge_b2, feats, bufC);
    // fwd GRU linear (C->2C)
    gemm_mma<128, 256, 0, false><<<dim3(128, 2, BVI), 256, GSMEM>>>(
        bufC, nullptr, wgh, wgl, nullptr, nullptr, hg);
    gru_scan4<<<dim3(16, CDIM, NB), 256>>>(hg, bufA);
    // bwd GRU linear (H-flips cancel -> forward scan)
    gemm_mma<128, 256, 0, false><<<dim3(128, 2, BVI), 256, GSMEM>>>(
        bufA, nullptr, wgbh, wgbl, nullptr, nullptr, hg);
    gru_scan4<<<dim3(16, CDIM, NB), 256>>>(hg, bufB);
    // alpha conv + softmax pool
    alpha_conv<<<dim3(64, 1, BVI), 256>>>(bufB, alpha_w, alpha_b, alp);
    pool_k4<<<dim3(16, 1, NB), 256>>>(bufB, alp, pool);
    // up 1x1 conv
    gemm_mma<128, 128, 0, false><<<dim3(128, 1, NB), 256, GSMEM>>>(
        pool, nullptr, wuph, wupl, up_b, nullptr, u);
    // pixel shuffle + outc 3x3
    outc_k<<<dim3(1024, 3, NB), 256>>>(u, outc_w, outc_b, (float*)d_out);
}

// round 12
// speedup vs baseline: 1.2187x; 1.0920x over previous
#include <cuda_runtime.h>
#include <cuda_bf16.h>
#include <math.h>
#include <stdint.h>

#define NPIX 16384
#define CDIM 128
#define NB 2
#define NV 6
#define BVI 12
#define WW 128

typedef uint16_t u16;
typedef uint32_t u32;

// ---------------- scratch ----------------
__device__ float g_bufA[(size_t)BVI * CDIM * NPIX];     // merge1 out (fp32)
__device__ float g_bufB[(size_t)BVI * CDIM * NPIX];     // g2 (fp32)
__device__ float g_hg  [(size_t)BVI * 2 * CDIM * NPIX]; // GRU linear out (fp32)
__device__ float g_alp [(size_t)BVI * NPIX];
__device__ float g_u   [(size_t)NB * CDIM * NPIX];
// bf16 hi/lo planes (GEMM B operands)
__device__ __align__(16) u16 g_dwh [(size_t)BVI * CDIM * NPIX], g_dwl [(size_t)BVI * CDIM * NPIX];
__device__ __align__(16) u16 g_m2h [(size_t)BVI * CDIM * NPIX], g_m2l [(size_t)BVI * CDIM * NPIX];
__device__ __align__(16) u16 g_g1h [(size_t)BVI * CDIM * NPIX], g_g1l [(size_t)BVI * CDIM * NPIX];
__device__ __align__(16) u16 g_plh [(size_t)NB * CDIM * NPIX],  g_pll [(size_t)NB * CDIM * NPIX];
// weight hi/lo planes (k-major rows)
__device__ __align__(16) u16 g_wm1h[128 * 256], g_wm1l[128 * 256];
__device__ __align__(16) u16 g_wm2h[128 * 128], g_wm2l[128 * 128];
__device__ __align__(16) u16 g_wgh [256 * 128], g_wgl [256 * 128];
__device__ __align__(16) u16 g_wgbh[256 * 128], g_wgbl[256 * 128];
__device__ __align__(16) u16 g_wuph[128 * 128], g_wupl[128 * 128];

__device__ __forceinline__ float gelu_exact(float x) {
    return 0.5f * x * (1.0f + erff(x * 0.70710678118654752f));
}
__device__ __forceinline__ u32 smem_u32(const void* p) {
    return (u32)__cvta_generic_to_shared(p);
}
__device__ __forceinline__ void split_pack(float v0, float v1, u32& hi, u32& lo) {
    asm("cvt.rn.bf16x2.f32 %0, %1, %2;" : "=r"(hi) : "f"(v1), "f"(v0));
    float r0 = v0 - __uint_as_float(hi << 16);
    float r1 = v1 - __uint_as_float(hi & 0xffff0000u);
    asm("cvt.rn.bf16x2.f32 %0, %1, %2;" : "=r"(lo) : "f"(r1), "f"(r0));
}
__device__ __forceinline__ void ldm_x4(u32* r, u32 addr) {
    asm volatile("ldmatrix.sync.aligned.m8n8.x4.shared.b16 {%0,%1,%2,%3}, [%4];"
                 : "=r"(r[0]), "=r"(r[1]), "=r"(r[2]), "=r"(r[3]) : "r"(addr));
}
__device__ __forceinline__ void ldm_x4t(u32* r, u32 addr) {
    asm volatile("ldmatrix.sync.aligned.m8n8.x4.trans.shared.b16 {%0,%1,%2,%3}, [%4];"
                 : "=r"(r[0]), "=r"(r[1]), "=r"(r[2]), "=r"(r[3]) : "r"(addr));
}
__device__ __forceinline__ void mma_bf16(float* d, const u32* a, const u32* b) {
    asm volatile(
        "mma.sync.aligned.m16n8k16.row.col.f32.bf16.bf16.f32 "
        "{%0,%1,%2,%3}, {%4,%5,%6,%7}, {%8,%9}, {%0,%1,%2,%3};"
        : "+f"(d[0]), "+f"(d[1]), "+f"(d[2]), "+f"(d[3])
        : "r"(a[0]), "r"(a[1]), "r"(a[2]), "r"(a[3]), "r"(b[0]), "r"(b[1]));
}
__device__ __forceinline__ void cpasync16(u32 dst, const void* src) {
    asm volatile("cp.async.cg.shared.global [%0], [%1], 16;" :: "r"(dst), "l"(src));
}
__device__ __forceinline__ void cp_commit() {
    asm volatile("cp.async.commit_group;" ::: "memory");
}

// ---------------- common tile constants ----------------
constexpr int KC = 32;
constexpr int A_PITCH_B = 80;
constexpr int A_PLANE_B = 128 * A_PITCH_B;       // 10240
constexpr int A_STAGE_B = 2 * A_PLANE_B;         // 20480 (hi+lo)
constexpr int BB_PITCH = 272;
constexpr int BB_PLANE = KC * BB_PITCH;          // 8704
constexpr int BB_STAGE = 2 * BB_PLANE;           // hi+lo 17408
constexpr int OFF_B0 = 2 * A_STAGE_B;            // 40960
constexpr int GSMEM  = OFF_B0 + 2 * BB_STAGE;    // 75776

// ================= GEMM-F32IN (merge1 only): fp32 B, register-staged convert ===========
template <int KTOT, int MTOT, int EPI, bool SPLIT>
__global__ __launch_bounds__(256, 2) void gemm_mma(
    const float* __restrict__ X0, const float* __restrict__ X1,
    const u16* __restrict__ Wh_g, const u16* __restrict__ Wl_g,
    const float* __restrict__ Bias, const float* __restrict__ Res,
    float* __restrict__ Out)
{
    extern __shared__ __align__(16) char sm[];
    const u32 sm0 = smem_u32(sm);

    const int img = blockIdx.z;
    const int p0  = blockIdx.x * 128;
    const int m0  = blockIdx.y * 128;
    const int tid = threadIdx.x;
    const int lane = tid & 31, wid = tid >> 5;
    const int wm = wid >> 2, wn = wid & 3;

    float acc[4][4][4];
#pragma unroll
    for (int i = 0; i < 4; i++)
#pragma unroll
        for (int j = 0; j < 4; j++)
#pragma unroll
            for (int q = 0; q < 4; q++) acc[i][j][q] = 0.f;

    constexpr int NCH = KTOT / KC;
    float4 breg[2][4];

    auto ldgB = [&](int c, int buf) {
        const int kbase = c * KC;
        const float* Xc = X0;
        int kb = kbase;
        if (SPLIT && kbase >= 128) { Xc = X1; kb = kbase - 128; }
        const size_t bbase = ((size_t)img * (SPLIT ? 128 : KTOT) + kb) * NPIX + p0;
#pragma unroll
        for (int i = 0; i < 4; i++) {
            int idx = tid + i * 256;
            int row = idx >> 5, seg = idx & 31;
            breg[buf][i] = *reinterpret_cast<const float4*>(
                Xc + bbase + (size_t)row * NPIX + seg * 4);
        }
    };
    auto copyA = [&](int c, int s) {
        const size_t abase = (size_t)m0 * KTOT + c * KC;
        const u32 adst = sm0 + s * A_STAGE_B;
#pragma unroll
        for (int i = 0; i < 4; i++) {
            int idx = tid + i * 256;
            int plane = idx >> 9, rem = idx & 511;
            int row = rem >> 2, seg = rem & 3;
            const u16* src = (plane ? Wl_g : Wh_g) + abase + (size_t)row * KTOT + seg * 8;
            cpasync16(adst + plane * A_PLANE_B + row * A_PITCH_B + seg * 16, src);
        }
    };

    const int lr  = lane & 7;
    const int lth = (lane >> 3) & 1;
    const int ltv = lane >> 4;
    const u32 a_row = (u32)(wm * 64 + lth * 8 + lr);

    ldgB(0, 0);
    copyA(0, 0); cp_commit();

#pragma unroll 1
    for (int c = 0; c < NCH; c++) {
        const int s = c & 1;
        if (c + 1 < NCH) ldgB(c + 1, s ^ 1);

        {
            const u32 bhoff = OFF_B0 + s * BB_STAGE;
#pragma unroll
            for (int i = 0; i < 4; i++) {
                int idx = tid + i * 256;
                int row = idx >> 5, seg = idx & 31;
                float4 v = breg[s][i];
                u32 h0, l0, h1, l1;
                split_pack(v.x, v.y, h0, l0);
                split_pack(v.z, v.w, h1, l1);
                u32 off = (u32)row * BB_PITCH + seg * 8;
                *reinterpret_cast<uint2*>(sm + bhoff + off) = make_uint2(h0, h1);
                *reinterpret_cast<uint2*>(sm + bhoff + BB_PLANE + off) = make_uint2(l0, l1);
            }
        }
        asm volatile("cp.async.wait_group 0;" ::: "memory");
        __syncthreads();

        if (c + 1 < NCH) { copyA(c + 1, s ^ 1); cp_commit(); }

        const u32 ah = sm0 + s * A_STAGE_B;
        const u32 al = ah + A_PLANE_B;
        const u32 bh = sm0 + OFF_B0 + s * BB_STAGE;
        const u32 bl = bh + BB_PLANE;

#pragma unroll
        for (int kk = 0; kk < KC / 16; kk++) {
            u32 af[4][4];
            u32 bfh[4][2], bfl[4][2];
            const u32 a_off = a_row * A_PITCH_B + kk * 32 + ltv * 16;
            const u32 b_off = (u32)(kk * 16 + lth * 8 + lr) * BB_PITCH + wn * 64 + ltv * 16;
#pragma unroll
            for (int mf = 0; mf < 4; mf++)
                ldm_x4(af[mf], ah + a_off + mf * 16 * A_PITCH_B);
#pragma unroll
            for (int nh = 0; nh < 2; nh++) {
                u32 r[4];
                ldm_x4t(r, bh + b_off + nh * 32);
                bfh[nh * 2][0] = r[0]; bfh[nh * 2][1] = r[1];
                bfh[nh * 2 + 1][0] = r[2]; bfh[nh * 2 + 1][1] = r[3];
            }
#pragma unroll
            for (int mf = 0; mf < 4; mf++)
#pragma unroll
                for (int nf = 0; nf < 4; nf++)
                    mma_bf16(acc[mf][nf], af[mf], bfh[nf]);
#pragma unroll
            for (int nh = 0; nh < 2; nh++) {
                u32 r[4];
                ldm_x4t(r, bl + b_off + nh * 32);
                bfl[nh * 2][0] = r[0]; bfl[nh * 2][1] = r[1];
                bfl[nh * 2 + 1][0] = r[2]; bfl[nh * 2 + 1][1] = r[3];
            }
#pragma unroll
            for (int mf = 0; mf < 4; mf++)
#pragma unroll
                for (int nf = 0; nf < 4; nf++)
                    mma_bf16(acc[mf][nf], af[mf], bfl[nf]);
#pragma unroll
            for (int mf = 0; mf < 4; mf++)
                ldm_x4(af[mf], al + a_off + mf * 16 * A_PITCH_B);
#pragma unroll
            for (int mf = 0; mf < 4; mf++)
#pragma unroll
                for (int nf = 0; nf < 4; nf++)
                    mma_bf16(acc[mf][nf], af[mf], bfh[nf]);
        }
    }

    const int g = lane >> 2, tg = lane & 3;
#pragma unroll
    for (int mf = 0; mf < 4; mf++) {
#pragma unroll
        for (int half = 0; half < 2; half++) {
            const int m = m0 + wm * 64 + mf * 16 + half * 8 + g;
            const float bias = Bias ? Bias[m] : 0.f;
            const size_t rowb = ((size_t)img * MTOT + m) * NPIX;
#pragma unroll
            for (int nf = 0; nf < 4; nf++) {
                const int px = p0 + wn * 32 + nf * 8 + 2 * tg;
                float v0 = acc[mf][nf][half * 2 + 0] + bias;
                float v1 = acc[mf][nf][half * 2 + 1] + bias;
                if (EPI == 1) { v0 = gelu_exact(v0); v1 = gelu_exact(v1); }
                *reinterpret_cast<float2*>(&Out[rowb + px]) = make_float2(v0, v1);
            }
        }
    }
}

// ================= GEMM-PLANES: B pre-split in global, pure cp.async mainloop ==========
// EPI: 0 bias-only; 2 bias+fp32 residual. OUTPL: write hi/lo planes else fp32.
template <int KTOT, int MTOT, int EPI, bool OUTPL>
__global__ __launch_bounds__(256, 2) void gemm_pl(
    const u16* __restrict__ Bh_g, const u16* __restrict__ Bl_g,
    const u16* __restrict__ Wh_g, const u16* __restrict__ Wl_g,
    const float* __restrict__ Bias, const float* __restrict__ Res,
    u16* __restrict__ OutH, u16* __restrict__ OutL, float* __restrict__ OutF)
{
    extern __shared__ __align__(16) char sm[];
    const u32 sm0 = smem_u32(sm);

    const int img = blockIdx.z;
    const int p0  = blockIdx.x * 128;
    const int m0  = blockIdx.y * 128;
    const int tid = threadIdx.x;
    const int lane = tid & 31, wid = tid >> 5;
    const int wm = wid >> 2, wn = wid & 3;

    float acc[4][4][4];
#pragma unroll
    for (int i = 0; i < 4; i++)
#pragma unroll
        for (int j = 0; j < 4; j++)
#pragma unroll
            for (int q = 0; q < 4; q++) acc[i][j][q] = 0.f;

    constexpr int NCH = KTOT / KC;

    auto copyAB = [&](int c, int s) {
        const int kbase = c * KC;
        // B planes
        const size_t bbase = ((size_t)img * KTOT + kbase) * NPIX + p0;
#pragma unroll
        for (int i = 0; i < 4; i++) {
            int idx = tid + i * 256;
            int plane = idx >> 9, rem = idx & 511;
            int row = rem >> 4, seg = rem & 15;
            const u16* src = (plane ? Bl_g : Bh_g) + bbase + (size_t)row * NPIX + seg * 8;
            cpasync16(sm0 + OFF_B0 + s * BB_STAGE + plane * BB_PLANE
                      + row * BB_PITCH + seg * 16, src);
        }
        // A planes
        const size_t abase = (size_t)m0 * KTOT + kbase;
        const u32 adst = sm0 + s * A_STAGE_B;
#pragma unroll
        for (int i = 0; i < 4; i++) {
            int idx = tid + i * 256;
            int plane = idx >> 9, rem = idx & 511;
            int row = rem >> 2, seg = rem & 3;
            const u16* src = (plane ? Wl_g : Wh_g) + abase + (size_t)row * KTOT + seg * 8;
            cpasync16(adst + plane * A_PLANE_B + row * A_PITCH_B + seg * 16, src);
        }
    };

    const int lr  = lane & 7;
    const int lth = (lane >> 3) & 1;
    const int ltv = lane >> 4;
    const u32 a_row = (u32)(wm * 64 + lth * 8 + lr);

    copyAB(0, 0); cp_commit();

#pragma unroll 1
    for (int c = 0; c < NCH; c++) {
        const int s = c & 1;
        asm volatile("cp.async.wait_group 0;" ::: "memory");   // A(c)+B(c) landed
        __syncthreads();   // MMA(c-1) reads of stage s^1 complete; stage s visible

        if (c + 1 < NCH) { copyAB(c + 1, s ^ 1); cp_commit(); }  // overlaps MMA(c)

        const u32 ah = sm0 + s * A_STAGE_B;
        const u32 al = ah + A_PLANE_B;
        const u32 bh = sm0 + OFF_B0 + s * BB_STAGE;
        const u32 bl = bh + BB_PLANE;

#pragma unroll
        for (int kk = 0; kk < KC / 16; kk++) {
            u32 af[4][4];
            u32 bfh[4][2], bfl[4][2];
            const u32 a_off = a_row * A_PITCH_B + kk * 32 + ltv * 16;
            const u32 b_off = (u32)(kk * 16 + lth * 8 + lr) * BB_PITCH + wn * 64 + ltv * 16;
#pragma unroll
            for (int mf = 0; mf < 4; mf++)
                ldm_x4(af[mf], ah + a_off + mf * 16 * A_PITCH_B);
#pragma unroll
            for (int nh = 0; nh < 2; nh++) {
                u32 r[4];
                ldm_x4t(r, bh + b_off + nh * 32);
                bfh[nh * 2][0] = r[0]; bfh[nh * 2][1] = r[1];
                bfh[nh * 2 + 1][0] = r[2]; bfh[nh * 2 + 1][1] = r[3];
            }
#pragma unroll
            for (int mf = 0; mf < 4; mf++)
#pragma unroll
                for (int nf = 0; nf < 4; nf++)
                    mma_bf16(acc[mf][nf], af[mf], bfh[nf]);
#pragma unroll
            for (int nh = 0; nh < 2; nh++) {
                u32 r[4];
                ldm_x4t(r, bl + b_off + nh * 32);
                bfl[nh * 2][0] = r[0]; bfl[nh * 2][1] = r[1];
                bfl[nh * 2 + 1][0] = r[2]; bfl[nh * 2 + 1][1] = r[3];
            }
#pragma unroll
            for (int mf = 0; mf < 4; mf++)
#pragma unroll
                for (int nf = 0; nf < 4; nf++)
                    mma_bf16(acc[mf][nf], af[mf], bfl[nf]);
#pragma unroll
            for (int mf = 0; mf < 4; mf++)
                ldm_x4(af[mf], al + a_off + mf * 16 * A_PITCH_B);
#pragma unroll
            for (int mf = 0; mf < 4; mf++)
#pragma unroll
                for (int nf = 0; nf < 4; nf++)
                    mma_bf16(acc[mf][nf], af[mf], bfh[nf]);
        }
    }

    const int g = lane >> 2, tg = lane & 3;
#pragma unroll
    for (int mf = 0; mf < 4; mf++) {
#pragma unroll
        for (int half = 0; half < 2; half++) {
            const int m = m0 + wm * 64 + mf * 16 + half * 8 + g;
            const float bias = Bias ? Bias[m] : 0.f;
            const size_t rowb = ((size_t)img * MTOT + m) * NPIX;
            const float* resrow = (EPI == 2) ? &Res[((size_t)img * CDIM + m) * NPIX] : nullptr;
#pragma unroll
            for (int nf = 0; nf < 4; nf++) {
                const int px = p0 + wn * 32 + nf * 8 + 2 * tg;
                float v0 = acc[mf][nf][half * 2 + 0] + bias;
                float v1 = acc[mf][nf][half * 2 + 1] + bias;
                if (EPI == 2) { v0 += resrow[px]; v1 += resrow[px + 1]; }
                if (OUTPL) {
                    u32 hi, lo;
                    split_pack(v0, v1, hi, lo);
                    const size_t hw = (rowb + px) >> 1;
                    reinterpret_cast<u32*>(OutH)[hw] = hi;
                    reinterpret_cast<u32*>(OutL)[hw] = lo;
                } else {
                    *reinterpret_cast<float2*>(&OutF[rowb + px]) = make_float2(v0, v1);
                }
            }
        }
    }
}

// ---------------- fused weight prep ----------------
__global__ void prep_w_all(
    const float* __restrict__ w1, const float* __restrict__ w2,
    const float* __restrict__ wg, const float* __restrict__ wgb,
    const float* __restrict__ wup,
    u16* __restrict__ w1h, u16* __restrict__ w1l,
    u16* __restrict__ w2h, u16* __restrict__ w2l,
    u16* __restrict__ wgh, u16* __restrict__ wgl,
    u16* __restrict__ wgbh, u16* __restrict__ wgbl,
    u16* __restrict__ wuph, u16* __restrict__ wupl)
{
    int i = blockIdx.x * 256 + threadIdx.x;
    const float* src; u16 *dh, *dl; int off;
    if      (i < 32768)  { src = w1;  dh = w1h;  dl = w1l;  off = i; }
    else if (i < 49152)  { src = w2;  dh = w2h;  dl = w2l;  off = i - 32768; }
    else if (i < 81920)  { src = wg;  dh = wgh;  dl = wgl;  off = i - 49152; }
    else if (i < 114688) { src = wgb; dh = wgbh; dl = wgbl; off = i - 81920; }
    else                 { src = wup; dh = wuph; dl = wupl; off = i - 114688; }
    float v = src[off];
    float hf = __bfloat162float(__float2bfloat16(v));
    dh[off] = (u16)(__float_as_uint(hf) >> 16);
    dl[off] = (u16)(__float_as_uint(__bfloat162float(__float2bfloat16(v - hf))) >> 16);
}

// ---------------- depthwise 3x3 + bias + GELU: fp32 in, planes out ----------------
__global__ __launch_bounds__(256) void dw3x3_pl(
    const float* __restrict__ in, const float* __restrict__ wd,
    const float* __restrict__ bd, u16* __restrict__ outH, u16* __restrict__ outL)
{
    int c = blockIdx.y, img = blockIdx.z;
    int pix0 = (blockIdx.x * 256 + threadIdx.x) * 2;
    int h = pix0 >> 7, w0 = pix0 & 127;
    const size_t base = ((size_t)img * CDIM + c) * NPIX;
    const float* p = in + base;
    float wreg[9];
#pragma unroll
    for (int i = 0; i < 9; i++) wreg[i] = wd[c * 9 + i];
    float s0 = bd[c], s1 = bd[c];
#pragma unroll
    for (int ky = 0; ky < 3; ky++) {
        int hh = h + ky - 1;
        if ((unsigned)hh >= 128u) continue;
#pragma unroll
        for (int kx = 0; kx < 3; kx++) {
            int w_a = w0 + kx - 1;
            int w_b = w0 + 1 + kx - 1;
            if ((unsigned)w_a < 128u) s0 = fmaf(wreg[ky * 3 + kx], p[hh * WW + w_a], s0);
            if ((unsigned)w_b < 128u) s1 = fmaf(wreg[ky * 3 + kx], p[hh * WW + w_b], s1);
        }
    }
    u32 hi, lo;
    split_pack(gelu_exact(s0), gelu_exact(s1), hi, lo);
    reinterpret_cast<u32*>(outH)[(base + pix0) >> 1] = hi;
    reinterpret_cast<u32*>(outL)[(base + pix0) >> 1] = lo;
}

// ---------------- minGRU scan (fp32 in); OUTPL: planes out else fp32 ----------------
template <bool OUTPL>
__global__ __launch_bounds__(256) void gru_scan4(
    const float* __restrict__ hg, float* __restrict__ gF,
    u16* __restrict__ gH, u16* __restrict__ gL)
{
    int c = blockIdx.y, b = blockIdx.z;
    int pix0 = (blockIdx.x * 256 + threadIdx.x) * 4;
    float4 h = make_float4(0.f, 0.f, 0.f, 0.f);
#pragma unroll
    for (int v = 0; v < NV; v++) {
        size_t base = (((size_t)(b * NV + v)) * 2 * CDIM + c) * NPIX + pix0;
        float4 hid = *reinterpret_cast<const float4*>(&hg[base]);
        float4 gt  = *reinterpret_cast<const float4*>(&hg[base + (size_t)CDIM * NPIX]);
        float z, ht;
        z = 1.f / (1.f + expf(-gt.x)); ht = (hid.x >= 0.f) ? (hid.x + 0.5f) : (1.f / (1.f + expf(-hid.x)));
        h.x = (1.f - z) * h.x + z * ht;
        z = 1.f / (1.f + expf(-gt.y)); ht = (hid.y >= 0.f) ? (hid.y + 0.5f) : (1.f / (1.f + expf(-hid.y)));
        h.y = (1.f - z) * h.y + z * ht;
        z = 1.f / (1.f + expf(-gt.z)); ht = (hid.z >= 0.f) ? (hid.z + 0.5f) : (1.f / (1.f + expf(-hid.z)));
        h.z = (1.f - z) * h.z + z * ht;
        z = 1.f / (1.f + expf(-gt.w)); ht = (hid.w >= 0.f) ? (hid.w + 0.5f) : (1.f / (1.f + expf(-hid.w)));
        h.w = (1.f - z) * h.w + z * ht;
        size_t d = (((size_t)(b * NV + v)) * CDIM + c) * NPIX + pix0;
        if (OUTPL) {
            u32 h0, l0, h1, l1;
            split_pack(h.x, h.y, h0, l0);
            split_pack(h.z, h.w, h1, l1);
            *reinterpret_cast<uint2*>(&gH[d]) = make_uint2(h0, h1);
            *reinterpret_cast<uint2*>(&gL[d]) = make_uint2(l0, l1);
        } else {
            *reinterpret_cast<float4*>(&gF[d]) = h;
        }
    }
}

// ---------------- alpha: 3x3 conv C->1 (fp32 in) ----------------
__global__ __launch_bounds__(256) void alpha_conv(
    const float* __restrict__ g2, const float* __restrict__ aw,
    const float* __restrict__ ab, float* __restrict__ alpha)
{
    __shared__ float w[1152];
    for (int i = threadIdx.x; i < 1152; i += 256) w[i] = aw[i];
    __syncthreads();
    int img = blockIdx.z;
    int pix = blockIdx.x * 256 + threadIdx.x;
    int h = pix >> 7, x = pix & 127;
    float s = ab[0];
    const float* base = g2 + (size_t)img * CDIM * NPIX;
    for (int c = 0; c < CDIM; c++) {
        const float* p  = base + (size_t)c * NPIX;
        const float* wc = w + c * 9;
#pragma unroll
        for (int ky = 0; ky < 3; ky++) {
            int hh = h + ky - 1;
            if ((unsigned)hh >= 128u) continue;
#pragma unroll
            for (int kx = 0; kx < 3; kx++) {
                int ww = x + kx - 1;
                if ((unsigned)ww >= 128u) continue;
                s = fmaf(wc[ky * 3 + kx], p[hh * WW + ww], s);
            }
        }
    }
    alpha[(size_t)img * NPIX + pix] = s;
}

// ---------------- softmax pool (fp32 in, planes out) ----------------
__global__ __launch_bounds__(256) void pool_k4pl(
    const float* __restrict__ g2, const float* __restrict__ alpha,
    u16* __restrict__ outH, u16* __restrict__ outL)
{
    int b = blockIdx.z;
    int pix0 = (blockIdx.x * 256 + threadIdx.x) * 4;
    float4 a[NV];
    float4 mx = make_float4(-1e30f, -1e30f, -1e30f, -1e30f);
#pragma unroll
    for (int v = 0; v < NV; v++) {
        a[v] = *reinterpret_cast<const float4*>(&alpha[(size_t)(b * NV + v) * NPIX + pix0]);
        mx.x = fmaxf(mx.x, a[v].x); mx.y = fmaxf(mx.y, a[v].y);
        mx.z = fmaxf(mx.z, a[v].z); mx.w = fmaxf(mx.w, a[v].w);
    }
    float4 sum = make_float4(0.f, 0.f, 0.f, 0.f);
#pragma unroll
    for (int v = 0; v < NV; v++) {
        a[v].x = expf(a[v].x - mx.x); sum.x += a[v].x;
        a[v].y = expf(a[v].y - mx.y); sum.y += a[v].y;
        a[v].z = expf(a[v].z - mx.z); sum.z += a[v].z;
        a[v].w = expf(a[v].w - mx.w); sum.w += a[v].w;
    }
    float4 inv = make_float4(1.f / sum.x, 1.f / sum.y, 1.f / sum.z, 1.f / sum.w);
#pragma unroll
    for (int v = 0; v < NV; v++) {
        a[v].x *= inv.x; a[v].y *= inv.y; a[v].z *= inv.z; a[v].w *= inv.w;
    }
    for (int c = 0; c < CDIM; c++) {
        float4 s = make_float4(0.f, 0.f, 0.f, 0.f);
#pragma unroll
        for (int v = 0; v < NV; v++) {
            float4 gv = *reinterpret_cast<const float4*>(
                &g2[(((size_t)(b * NV + v)) * CDIM + c) * NPIX + pix0]);
            s.x = fmaf(a[v].x, gv.x, s.x);
            s.y = fmaf(a[v].y, gv.y, s.y);
            s.z = fmaf(a[v].z, gv.z, s.z);
            s.w = fmaf(a[v].w, gv.w, s.w);
        }
        size_t d = ((size_t)b * CDIM + c) * NPIX + pix0;
        u32 h0, l0, h1, l1;
        split_pack(s.x, s.y, h0, l0);
        split_pack(s.z, s.w, h1, l1);
        *reinterpret_cast<uint2*>(&outH[d]) = make_uint2(h0, h1);
        *reinterpret_cast<uint2*>(&outL[d]) = make_uint2(l0, l1);
    }
}

// ---------------- pixel-shuffle(4) + 3x3 conv 8->3 (512->512 resize = identity) --------
__global__ __launch_bounds__(256) void outc_k(
    const float* __restrict__ u, const float* __restrict__ wt,
    const float* __restrict__ bs, float* __restrict__ out)
{
    __shared__ float w[216];
    if (threadIdx.x < 216) w[threadIdx.x] = wt[threadIdx.x];
    __syncthreads();
    int b = blockIdx.z, co = blockIdx.y;
    int idx = blockIdx.x * 256 + threadIdx.x;
    int y = idx >> 9, x = idx & 511;
    float s = bs[co];
    const float* ub = u + (size_t)b * CDIM * NPIX;
#pragma unroll
    for (int ky = 0; ky < 3; ky++) {
        int yy = y + ky - 1;
        if ((unsigned)yy >= 512u) continue;
        int sy = yy & 3, hy = yy >> 2;
#pragma unroll
        for (int kx = 0; kx < 3; kx++) {
            int xx = x + kx - 1;
            if ((unsigned)xx >= 512u) continue;
            int sx = xx & 3, hx = xx >> 2;
            const float* up = ub + (size_t)(sy * 4 + sx) * NPIX + hy * WW + hx;
#pragma unroll
            for (int ci = 0; ci < 8; ci++)
                s = fmaf(w[(co * 8 + ci) * 9 + ky * 3 + kx], up[(size_t)ci * 16 * NPIX], s);
        }
    }
    out[((size_t)b * 3 + co) * (512 * 512) + idx] = s;
}

// ---------------- launch ----------------
extern "C" void kernel_launch(void* const* d_in, const int* in_sizes, int n_in,
                              void* d_out, int out_size)
{
    const float* feats     = (const float*)d_in[0];
    const float* prj       = (const float*)d_in[1];
    const float* merge_w1  = (const float*)d_in[2];
    const float* merge_b1  = (const float*)d_in[3];
    const float* merge_wd  = (const float*)d_in[4];
    const float* merge_bd  = (const float*)d_in[5];
    const float* merge_w2  = (const float*)d_in[6];
    const float* merge_b2  = (const float*)d_in[7];
    const float* gru_w     = (const float*)d_in[8];
    const float* gru_bw    = (const float*)d_in[9];
    const float* alpha_w   = (const float*)d_in[10];
    const float* alpha_b   = (const float*)d_in[11];
    const float* up_w      = (const float*)d_in[12];
    const float* up_b      = (const float*)d_in[13];
    const float* outc_w    = (const float*)d_in[14];
    const float* outc_b    = (const float*)d_in[15];

    float *bufA, *bufB, *hg, *alp, *u;
    u16 *dwh, *dwl, *m2h, *m2l, *g1h, *g1l, *plh, *pll;
    u16 *wm1h, *wm1l, *wm2h, *wm2l, *wgh, *wgl, *wgbh, *wgbl, *wuph, *wupl;
    cudaGetSymbolAddress((void**)&bufA, g_bufA);
    cudaGetSymbolAddress((void**)&bufB, g_bufB);
    cudaGetSymbolAddress((void**)&hg,   g_hg);
    cudaGetSymbolAddress((void**)&alp,  g_alp);
    cudaGetSymbolAddress((void**)&u,    g_u);
    cudaGetSymbolAddress((void**)&dwh,  g_dwh);  cudaGetSymbolAddress((void**)&dwl,  g_dwl);
    cudaGetSymbolAddress((void**)&m2h,  g_m2h);  cudaGetSymbolAddress((void**)&m2l,  g_m2l);
    cudaGetSymbolAddress((void**)&g1h,  g_g1h);  cudaGetSymbolAddress((void**)&g1l,  g_g1l);
    cudaGetSymbolAddress((void**)&plh,  g_plh);  cudaGetSymbolAddress((void**)&pll,  g_pll);
    cudaGetSymbolAddress((void**)&wm1h, g_wm1h); cudaGetSymbolAddress((void**)&wm1l, g_wm1l);
    cudaGetSymbolAddress((void**)&wm2h, g_wm2h); cudaGetSymbolAddress((void**)&wm2l, g_wm2l);
    cudaGetSymbolAddress((void**)&wgh,  g_wgh);  cudaGetSymbolAddress((void**)&wgl,  g_wgl);
    cudaGetSymbolAddress((void**)&wgbh, g_wgbh); cudaGetSymbolAddress((void**)&wgbl, g_wgbl);
    cudaGetSymbolAddress((void**)&wuph, g_wuph); cudaGetSymbolAddress((void**)&wupl, g_wupl);

    cudaFuncSetAttribute(gemm_mma<256, 128, 1, true >, cudaFuncAttributeMaxDynamicSharedMemorySize, GSMEM);
    cudaFuncSetAttribute(gemm_pl<128, 128, 2, true >,  cudaFuncAttributeMaxDynamicSharedMemorySize, GSMEM);
    cudaFuncSetAttribute(gemm_pl<128, 256, 0, false>,  cudaFuncAttributeMaxDynamicSharedMemorySize, GSMEM);
    cudaFuncSetAttribute(gemm_pl<128, 128, 0, false>,  cudaFuncAttributeMaxDynamicSharedMemorySize, GSMEM);

    prep_w_all<<<512, 256>>>(merge_w1, merge_w2, gru_w, gru_bw, up_w,
                             wm1h, wm1l, wm2h, wm2l, wgh, wgl, wgbh, wgbl, wuph, wupl);

    // merge1: 1x1 (2C->C) + GELU (fp32 out)
    gemm_mma<256, 128, 1, true ><<<dim3(128, 1, BVI), 256, GSMEM>>>(
        feats, prj, wm1h, wm1l, merge_b1, nullptr, bufA);
    // depthwise 3x3 + GELU -> planes
    dw3x3_pl<<<dim3(32, CDIM, BVI), 256>>>(bufA, merge_wd, merge_bd, dwh, dwl);
    // merge2: planes in, bias + residual(feats), planes out
    gemm_pl<128, 128, 2, true ><<<dim3(128, 1, BVI), 256, GSMEM>>>(
        dwh, dwl, wm2h, wm2l, merge_b2, feats, m2h, m2l, nullptr);
    // fwd GRU linear: planes in, fp32 hg out
    gemm_pl<128, 256, 0, false><<<dim3(128, 2, BVI), 256, GSMEM>>>(
        m2h, m2l, wgh, wgl, nullptr, nullptr, nullptr, nullptr, hg);
    gru_scan4<true ><<<dim3(16, CDIM, NB), 256>>>(hg, nullptr, g1h, g1l);
    // bwd GRU linear (H-flips cancel -> forward scan): planes in, fp32 hg out
    gemm_pl<128, 256, 0, false><<<dim3(128, 2, BVI), 256, GSMEM>>>(
        g1h, g1l, wgbh, wgbl, nullptr, nullptr, nullptr, nullptr, hg);
    gru_scan4<false><<<dim3(16, CDIM, NB), 256>>>(hg, bufB, nullptr, nullptr);
    // alpha conv + softmax pool (fp32 in, planes out)
    alpha_conv<<<dim3(64, 1, BVI), 256>>>(bufB, alpha_w, alpha_b, alp);
    pool_k4pl<<<dim3(16, 1, NB), 256>>>(bufB, alp, plh, pll);
    // up: planes in, fp32 out
    gemm_pl<128, 128, 0, false><<<dim3(128, 1, NB), 256, GSMEM>>>(
        plh, pll, wuph, wupl, up_b, nullptr, nullptr, nullptr, u);
    // pixel shuffle + outc 3x3
    outc_k<<<dim3(1024, 3, NB), 256>>>(u, outc_w, outc_b, (float*)d_out);
}